// round 14
// baseline (speedup 1.0000x reference)
#include <cuda_runtime.h>
#include <cuda_fp16.h>
#include <cstdint>

#define PP 6400
#define HH 80
#define WW 80
#define KC 256      // inner dim of correlation GEMM
#define CH 324      // real channels per direction
#define CP 384      // padded channel stride
#define CIE 352     // ci loop end (324 rounded up to 32)

#define GST 4       // gemm pipeline stages (BK=16)
#define CST 3       // conv pipeline stages (BK=32)
#define PADKG 24    // gemm smem row: 16 used + 8 pad halfs
#define STGHG 3072  // gemm halfs per stage per operand: 128 * PADKG
#define PADKC 40    // conv smem row: 32 used + 8 pad halfs
#define STGHC 5120  // conv halfs per stage per operand: 128 * PADKC

// ---------------- scratch (static device globals; no allocs) ----------------
__device__ __half g_corr0[(size_t)PP * PP];   // corr01  (P, 80, 80) fp16
__device__ __half g_corr1[(size_t)PP * PP];   // corr10 = corr01^T   fp16
__device__ __half g_f0h[PP * KC];             // fp16 f0, [p][k]
__device__ __half g_f1h[PP * KC];             // fp16 f1, [q][k]
__device__ __half g_feat[2 * PP * CP];        // lookup features (fp16), both branches
__device__ __half g_t1[2 * PP * CP];          // conv1 output (fp16)
__device__ float  g_t2[2 * PP * CP];          // conv2 output (fp32)
__device__ __half g_w1[9 * CP * CIE];         // [tap][co][ci] fp16
__device__ __half g_w2[9 * CP * CIE];

// ---------------- helpers ----------------
__device__ __forceinline__ void mma_f16(float4& c,
                                        uint32_t a0, uint32_t a1, uint32_t a2, uint32_t a3,
                                        uint32_t b0, uint32_t b1) {
    asm volatile(
        "mma.sync.aligned.m16n8k16.row.col.f32.f16.f16.f32 "
        "{%0,%1,%2,%3}, {%4,%5,%6,%7}, {%8,%9}, {%0,%1,%2,%3};"
        : "+f"(c.x), "+f"(c.y), "+f"(c.z), "+f"(c.w)
        : "r"(a0), "r"(a1), "r"(a2), "r"(a3), "r"(b0), "r"(b1));
}

__device__ __forceinline__ uint32_t ld32h(const __half* p) {
    return *(const uint32_t*)p;
}

__device__ __forceinline__ uint32_t su32(const void* p) {
    uint32_t a;
    asm("{ .reg .u64 t; cvta.to.shared.u64 t, %1; cvt.u32.u64 %0, t; }"
        : "=r"(a) : "l"(p));
    return a;
}

__device__ __forceinline__ void cpa16(uint32_t dst, const void* src, bool v) {
    asm volatile("cp.async.cg.shared.global [%0], [%1], 16, %2;"
                 :: "r"(dst), "l"(src), "r"(v ? 16 : 0));
}
__device__ __forceinline__ void cpa_commit() {
    asm volatile("cp.async.commit_group;");
}
template <int N>
__device__ __forceinline__ void cpa_wait() {
    asm volatile("cp.async.wait_group %0;" :: "n"(N));
}

// ---------------- transpose + fp16 convert: (KC, PP) -> [p][KC] half ----------------
__global__ void transh_k(const float* __restrict__ in, __half* __restrict__ out) {
    __shared__ float t[32][33];
    const int p0 = blockIdx.x * 32;
    const int k0 = blockIdx.y * 32;
    const int tx = threadIdx.x;
#pragma unroll
    for (int r = threadIdx.y; r < 32; r += 8)
        t[r][tx] = in[(size_t)(k0 + r) * PP + p0 + tx];
    __syncthreads();
#pragma unroll
    for (int r = threadIdx.y; r < 32; r += 8)
        out[(size_t)(p0 + r) * KC + k0 + tx] = __float2half(t[tx][r]);
}

// ---------------- weight repack: (3,3,324,324) HWIO -> [tap][co(384)][ci(352)] fp16 ----
__global__ void repack_w(const float* __restrict__ w1, const float* __restrict__ w2,
                         __half* __restrict__ wp1, __half* __restrict__ wp2) {
    const int id = blockIdx.x * blockDim.x + threadIdx.x;
    if (id >= 9 * CP * CIE) return;
    const float* w = blockIdx.y ? w2 : w1;
    __half* wp = blockIdx.y ? wp2 : wp1;
    const int ci = id % CIE;
    const int t = id / CIE;
    const int co = t % CP;
    const int tap = t / CP;
    const float v = (ci < CH && co < CH) ? w[((size_t)(tap * CH + ci)) * CH + co] : 0.f;
    wp[id] = __float2half(v);
}

// ---------------- fp16 tensor-core GEMM writing C and C^T (fp16 corr output) ----------
// A = f0h [p][KC], B = f1h [q][KC]. 128x128 tile, BK=16 (one k16 mma phase/slab),
// GST-stage cp.async pipeline. 8 warps (2x4), warp tile 64x32.
__global__ __launch_bounds__(256) void gemm_tc(const __half* __restrict__ A,
                                               const __half* __restrict__ B,
                                               __half* __restrict__ C0,
                                               __half* __restrict__ C1) {
    extern __shared__ __align__(16) __half smh[];
    __half* Asb = smh;                      // GST stages of [128][PADKG]
    __half* Bsb = smh + GST * STGHG;
    const uint32_t asu = su32(Asb);
    const uint32_t bsu = su32(Bsb);

    const int tid = threadIdx.x;
    const int p0 = blockIdx.y * 128;
    const int q0 = blockIdx.x * 128;
    const int warp = tid >> 5, lane = tid & 31;
    const int wm = warp >> 2, wn = warp & 3;   // 2 x 4
    const int m0 = wm * 64, n0 = wn * 32;
    const int lr = lane >> 2, lc4 = lane & 3;
    const int arow = tid >> 1;              // loader row 0..127
    const int aseg = (tid & 1) * 8;         // halfs (16 B)

    float4 acc[4][4];
#pragma unroll
    for (int i = 0; i < 4; i++)
#pragma unroll
        for (int j = 0; j < 4; j++) acc[i][j] = make_float4(0.f, 0.f, 0.f, 0.f);

    const __half* Ap = A + (size_t)(p0 + arow) * KC + aseg;
    const __half* Bp = B + (size_t)(q0 + arow) * KC + aseg;
    const uint32_t adst = asu + (uint32_t)(arow * PADKG + aseg) * 2;
    const uint32_t bdst = bsu + (uint32_t)(arow * PADKG + aseg) * 2;

#define GEMM_ISSUE(SLAB, BUF)                                                      \
    do {                                                                           \
        const int koff = (SLAB) * 16;                                              \
        cpa16(adst + (BUF) * (STGHG * 2), Ap + koff, true);                        \
        cpa16(bdst + (BUF) * (STGHG * 2), Bp + koff, true);                        \
        cpa_commit();                                                              \
    } while (0)

    const int NSLAB = KC / 16;   // 16
#pragma unroll
    for (int s = 0; s < GST - 1; s++) GEMM_ISSUE(s, s);

    for (int it = 0; it < NSLAB; ++it) {
        cpa_wait<GST - 2>();
        __syncthreads();
        if (it + GST - 1 < NSLAB) GEMM_ISSUE(it + GST - 1, (it + GST - 1) % GST);
        const __half* Asf = Asb + (it % GST) * STGHG;
        const __half* Bsf = Bsb + (it % GST) * STGHG;
        uint32_t bf[4][2];
#pragma unroll
        for (int j = 0; j < 4; j++) {
            const int nb = n0 + j * 8 + lr;
            bf[j][0] = ld32h(Bsf + nb * PADKG + lc4 * 2);
            bf[j][1] = ld32h(Bsf + nb * PADKG + lc4 * 2 + 8);
        }
#pragma unroll
        for (int i = 0; i < 4; i++) {
            const int mb = m0 + i * 16 + lr;
            const uint32_t a0 = ld32h(Asf + mb * PADKG + lc4 * 2);
            const uint32_t a1 = ld32h(Asf + (mb + 8) * PADKG + lc4 * 2);
            const uint32_t a2 = ld32h(Asf + mb * PADKG + lc4 * 2 + 8);
            const uint32_t a3 = ld32h(Asf + (mb + 8) * PADKG + lc4 * 2 + 8);
#pragma unroll
            for (int j = 0; j < 4; j++)
                mma_f16(acc[i][j], a0, a1, a2, a3, bf[j][0], bf[j][1]);
        }
    }
#undef GEMM_ISSUE

#pragma unroll
    for (int i = 0; i < 4; i++) {
        const int r = p0 + m0 + i * 16 + lr;
#pragma unroll
        for (int j = 0; j < 4; j++) {
            const int c = q0 + n0 + j * 8 + lc4 * 2;
            const __half hx = __float2half(acc[i][j].x);
            const __half hy = __float2half(acc[i][j].y);
            const __half hz = __float2half(acc[i][j].z);
            const __half hw = __float2half(acc[i][j].w);
            *(__half2*)&C0[(size_t)r * PP + c]       = __halves2half2(hx, hy);
            *(__half2*)&C0[(size_t)(r + 8) * PP + c] = __halves2half2(hz, hw);
            C1[(size_t)c * PP + r]           = hx;
            C1[(size_t)(c + 1) * PP + r]     = hy;
            C1[(size_t)c * PP + r + 8]       = hz;
            C1[(size_t)(c + 1) * PP + r + 8] = hw;
        }
    }
}

// ---------------- fused pyramid + lookup (fp16 corr input, fp32 math, fp16 out) -------
__global__ __launch_bounds__(256) void pyrlook_k(const __half* __restrict__ corr0,
                                                 const __half* __restrict__ corr1,
                                                 __half* __restrict__ feat) {
    __shared__ float L1[1600];
    __shared__ float L2[400];
    __shared__ float L3[100];
    const int p = blockIdx.x;
    const int br = blockIdx.y;
    const __half* row = (br ? corr1 : corr0) + (size_t)p * PP;

    for (int i = threadIdx.x; i < 1600; i += 256) {
        const int y = i / 40, x = i % 40;
        const float2 a = __half22float2(*(const __half2*)(row + y * 160 + x * 2));
        const float2 b = __half22float2(*(const __half2*)(row + y * 160 + 80 + x * 2));
        L1[i] = 0.25f * (a.x + a.y + b.x + b.y);
    }
    __syncthreads();
    for (int i = threadIdx.x; i < 400; i += 256) {
        const int y = i / 20, x = i % 20;
        const float* m = L1 + y * 80 + x * 2;
        L2[i] = 0.25f * (m[0] + m[1] + m[40] + m[41]);
    }
    __syncthreads();
    for (int i = threadIdx.x; i < 100; i += 256) {
        const int y = i / 10, x = i % 10;
        const float* m = L2 + y * 40 + x * 2;
        L3[i] = 0.25f * (m[0] + m[1] + m[20] + m[21]);
    }
    __syncthreads();

    const int px = p % WW, py = p / WW;
    __half* out = feat + ((size_t)br * PP + p) * CP;
    for (int ch = threadIdx.x; ch < CP; ch += 256) {
        float v = 0.f;
        if (ch < 81) {
            const int dx = ch / 9 - 4;
            const int dy = ch % 9 - 4;
            const int ix = px + dx, iy = py + dy;
            if (((unsigned)ix < (unsigned)WW) && ((unsigned)iy < (unsigned)HH))
                v = __half2float(row[iy * WW + ix]);
        } else if (ch < CH) {
            const int lvl = ch / 81;
            const int off = ch % 81;
            const int dx = off / 9 - 4;
            const int dy = off % 9 - 4;
            const float* base;
            int hl;
            switch (lvl) {
                case 1: base = L1; hl = 40; break;
                case 2: base = L2; hl = 20; break;
                default: base = L3; hl = 10; break;
            }
            const int wl = hl;
            const float s = (float)(1 << lvl);
            const float cx = (2.f * px + 1.f) / (2.f * s) - 0.5f + (float)dx;
            const float cy = (2.f * py + 1.f) / (2.f * s) - 0.5f + (float)dy;
            const float x0f = floorf(cx), y0f = floorf(cy);
            const int ix = (int)x0f, iy = (int)y0f;
            const float fx = cx - x0f, fy = cy - y0f;
            float v00 = 0.f, v10 = 0.f, v01 = 0.f, v11 = 0.f;
            const bool xv0 = (ix >= 0) & (ix < wl);
            const bool xv1 = (ix + 1 >= 0) & (ix + 1 < wl);
            const bool yv0 = (iy >= 0) & (iy < hl);
            const bool yv1 = (iy + 1 >= 0) & (iy + 1 < hl);
            if (yv0) {
                if (xv0) v00 = base[iy * wl + ix];
                if (xv1) v10 = base[iy * wl + ix + 1];
            }
            if (yv1) {
                if (xv0) v01 = base[(iy + 1) * wl + ix];
                if (xv1) v11 = base[(iy + 1) * wl + ix + 1];
            }
            v = v00 * (1.f - fx) * (1.f - fy) + v10 * fx * (1.f - fy)
              + v01 * (1.f - fx) * fy + v11 * fx * fy;
        }
        out[ch] = __float2half(v);
    }
}

// ---------------- 3x3 conv as implicit GEMM (fp16), BK=32, CST-stage pipeline ---------
// M=12800 (BM=128), N=384 (BN=128), K=9 taps x 352, BK=32 (two k16 phases/slab).
// 8 warps (2x4), warp tile 64x32. Epilogue relu(acc+bias) [+res].
template <int ADD_RES>
__global__ __launch_bounds__(256, 2) void conv_tc(const __half* __restrict__ X,
                                                  const __half* __restrict__ Wt,
                                                  const float* __restrict__ bias,
                                                  const __half* __restrict__ res,
                                                  void* __restrict__ Yout) {
    extern __shared__ __align__(16) __half smh[];
    __half* Asb = smh;                      // CST stages of [128][PADKC]
    __half* Bsb = smh + CST * STGHC;
    const uint32_t asu = su32(Asb);
    const uint32_t bsu = su32(Bsb);

    const int tid = threadIdx.x;
    const int p0 = blockIdx.x * 128;
    const int c0 = blockIdx.y * 128;
    const int warp = tid >> 5, lane = tid & 31;
    const int wm = warp >> 2, wn = warp & 3;   // 2 x 4
    const int m0 = wm * 64, n0 = wn * 32;
    const int lr = lane >> 2, lc4 = lane & 3;

    const int arow = tid >> 1;              // loader row 0..127
    const int aseg = (tid & 1) * 16;        // halfs
    const int pl = (p0 + arow) % PP;
    const int apy = pl / WW, apx = pl % WW;

    const uint32_t adst = asu + (uint32_t)(arow * PADKC + aseg) * 2;
    const uint32_t bdst = bsu + (uint32_t)(arow * PADKC + aseg) * 2;
    const __half* Xr = X + (size_t)(p0 + arow) * CP + aseg;
    const __half* Wr = Wt + (size_t)(c0 + arow) * CIE + aseg;

    float4 acc[4][4];
#pragma unroll
    for (int i = 0; i < 4; i++)
#pragma unroll
        for (int j = 0; j < 4; j++) acc[i][j] = make_float4(0.f, 0.f, 0.f, 0.f);

#define CONV_ISSUE(SLAB, BUF)                                                        \
    do {                                                                             \
        const int tap_ = (SLAB) / 11;                                                \
        const int kb_ = ((SLAB) % 11) * 32;                                          \
        const int dy = tap_ / 3 - 1, dx = tap_ % 3 - 1;                              \
        const bool valid = ((unsigned)(apy + dy) < (unsigned)HH) &&                  \
                           ((unsigned)(apx + dx) < (unsigned)WW);                    \
        const __half* xs = Xr + (size_t)(dy * WW + dx) * CP + kb_;                   \
        cpa16(adst + (BUF) * (STGHC * 2), xs, valid);                                \
        cpa16(adst + (BUF) * (STGHC * 2) + 16, xs + 8, valid);                       \
        const __half* ws = Wr + (size_t)tap_ * (CP * CIE) + kb_;                     \
        cpa16(bdst + (BUF) * (STGHC * 2), ws, true);                                 \
        cpa16(bdst + (BUF) * (STGHC * 2) + 16, ws + 8, true);                        \
        cpa_commit();                                                                \
    } while (0)

    const int NIT = 9 * 11;   // 99
#pragma unroll
    for (int s = 0; s < CST - 1; s++) CONV_ISSUE(s, s);

    for (int it = 0; it < NIT; ++it) {
        cpa_wait<CST - 2>();
        __syncthreads();
        if (it + CST - 1 < NIT) CONV_ISSUE(it + CST - 1, (it + CST - 1) % CST);
        const __half* Asf = Asb + (it % CST) * STGHC;
        const __half* Bsf = Bsb + (it % CST) * STGHC;
#pragma unroll
        for (int ks = 0; ks < 32; ks += 16) {
            uint32_t bf[4][2];
#pragma unroll
            for (int j = 0; j < 4; j++) {
                const int nb = n0 + j * 8 + lr;
                bf[j][0] = ld32h(Bsf + nb * PADKC + ks + lc4 * 2);
                bf[j][1] = ld32h(Bsf + nb * PADKC + ks + lc4 * 2 + 8);
            }
#pragma unroll
            for (int i = 0; i < 4; i++) {
                const int mb = m0 + i * 16 + lr;
                const uint32_t a0 = ld32h(Asf + mb * PADKC + ks + lc4 * 2);
                const uint32_t a1 = ld32h(Asf + (mb + 8) * PADKC + ks + lc4 * 2);
                const uint32_t a2 = ld32h(Asf + mb * PADKC + ks + lc4 * 2 + 8);
                const uint32_t a3 = ld32h(Asf + (mb + 8) * PADKC + ks + lc4 * 2 + 8);
#pragma unroll
                for (int j = 0; j < 4; j++)
                    mma_f16(acc[i][j], a0, a1, a2, a3, bf[j][0], bf[j][1]);
            }
        }
    }
#undef CONV_ISSUE

#pragma unroll
    for (int i = 0; i < 4; i++) {
        const int r0 = p0 + m0 + i * 16 + lr;
#pragma unroll
        for (int j = 0; j < 4; j++) {
            const int c = c0 + n0 + j * 8 + lc4 * 2;
            const float bv0 = (c < CH) ? bias[c] : 0.f;
            const float bv1 = (c + 1 < CH) ? bias[c + 1] : 0.f;
            float vx = fmaxf(acc[i][j].x + bv0, 0.f);
            float vy = fmaxf(acc[i][j].y + bv1, 0.f);
            float vz = fmaxf(acc[i][j].z + bv0, 0.f);
            float vw = fmaxf(acc[i][j].w + bv1, 0.f);
            if (ADD_RES) {
                const float2 r0v = __half22float2(*(const __half2*)&res[(size_t)r0 * CP + c]);
                const float2 r1v = __half22float2(*(const __half2*)&res[(size_t)(r0 + 8) * CP + c]);
                float* Yf = (float*)Yout;
                *(float2*)&Yf[(size_t)r0 * CP + c]       = make_float2(vx + r0v.x, vy + r0v.y);
                *(float2*)&Yf[(size_t)(r0 + 8) * CP + c] = make_float2(vz + r1v.x, vw + r1v.y);
            } else {
                __half* Yh = (__half*)Yout;
                *(__half2*)&Yh[(size_t)r0 * CP + c]       = __floats2half2_rn(vx, vy);
                *(__half2*)&Yh[(size_t)(r0 + 8) * CP + c] = __floats2half2_rn(vz, vw);
            }
        }
    }
}

// ---------------- LayerNorm over 324 channels + NHWC -> NCHW store (both branches) ----
__global__ __launch_bounds__(256) void ln_k(const float* __restrict__ Yin,
                                            const float* __restrict__ g,
                                            const float* __restrict__ bta,
                                            float* __restrict__ out) {
    __shared__ float tile[CH][33];
    const int br = blockIdx.y;
    const int p0 = blockIdx.x * 32;
    const float* Ybr = Yin + (size_t)br * PP * CP;
    const int cbase = br * CH;
    const int warp = threadIdx.x >> 5, lane = threadIdx.x & 31;
#pragma unroll
    for (int r = 0; r < 4; r++) {
        const int lp = warp + r * 8;
        const float* row = Ybr + (size_t)(p0 + lp) * CP;
        float vals[11];
        float s = 0.f, sq = 0.f;
#pragma unroll
        for (int j = 0; j < 11; j++) {
            const int ch = lane + j * 32;
            float v = (ch < CH) ? row[ch] : 0.f;
            vals[j] = v;
            s += v;
            sq += v * v;
        }
#pragma unroll
        for (int o = 16; o; o >>= 1) {
            s += __shfl_xor_sync(0xffffffffu, s, o);
            sq += __shfl_xor_sync(0xffffffffu, sq, o);
        }
        const float mean = s * (1.f / 324.f);
        const float var = sq * (1.f / 324.f) - mean * mean;
        const float inv = rsqrtf(var + 1e-5f);
#pragma unroll
        for (int j = 0; j < 11; j++) {
            const int ch = lane + j * 32;
            if (ch < CH)
                tile[ch][lp] = (vals[j] - mean) * inv * g[ch] + bta[ch];
        }
    }
    __syncthreads();
    const int col = threadIdx.x & 31;
    for (int ch = threadIdx.x >> 5; ch < CH; ch += 8)
        out[(size_t)(cbase + ch) * PP + p0 + col] = tile[ch][col];
}

// ---------------- launch ----------------
extern "C" void kernel_launch(void* const* d_in, const int* in_sizes, int n_in,
                              void* d_out, int out_size) {
    const float* f0  = (const float*)d_in[0];
    const float* f1  = (const float*)d_in[1];
    const float* w1  = (const float*)d_in[2];
    const float* b1  = (const float*)d_in[3];
    const float* w2  = (const float*)d_in[4];
    const float* b2  = (const float*)d_in[5];
    const float* lng = (const float*)d_in[6];
    const float* lnb = (const float*)d_in[7];
    float* out = (float*)d_out;

    float *t2;
    __half *corr0, *corr1, *f0h, *f1h, *ft, *t1, *wp1, *wp2;
    cudaGetSymbolAddress((void**)&corr0, g_corr0);
    cudaGetSymbolAddress((void**)&corr1, g_corr1);
    cudaGetSymbolAddress((void**)&f0h, g_f0h);
    cudaGetSymbolAddress((void**)&f1h, g_f1h);
    cudaGetSymbolAddress((void**)&ft, g_feat);
    cudaGetSymbolAddress((void**)&t1, g_t1);
    cudaGetSymbolAddress((void**)&t2, g_t2);
    cudaGetSymbolAddress((void**)&wp1, g_w1);
    cudaGetSymbolAddress((void**)&wp2, g_w2);

    const int gemm_smem = GST * STGHG * 2 * 2;   // 49152 B
    const int conv_smem = CST * STGHC * 2 * 2;   // 61440 B
    cudaFuncSetAttribute(gemm_tc, cudaFuncAttributeMaxDynamicSharedMemorySize, gemm_smem);
    cudaFuncSetAttribute(conv_tc<0>, cudaFuncAttributeMaxDynamicSharedMemorySize, conv_smem);
    cudaFuncSetAttribute(conv_tc<1>, cudaFuncAttributeMaxDynamicSharedMemorySize, conv_smem);

    // 0,1: transpose + fp16 convert of f0/f1 -> [p][k]
    transh_k<<<dim3(200, 8), dim3(32, 8)>>>(f0, f0h);
    transh_k<<<dim3(200, 8), dim3(32, 8)>>>(f1, f1h);
    // 2: weight repack (both sets) -> [tap][co][ci] fp16
    repack_w<<<dim3((9 * CP * CIE + 255) / 256, 2), 256>>>(w1, w2, wp1, wp2);
    // 3: correlation GEMM (fp16 MMA) writing corr01 and corr10 (fp16)
    gemm_tc<<<dim3(50, 50), 256, gemm_smem>>>(f0h, f1h, corr0, corr1);
    // 4: fused pyramid + lookup (both branches, fp16 corr in, fp16 feat out)
    pyrlook_k<<<dim3(PP, 2), 256>>>(corr0, corr1, ft);
    // 5,6: convs, both branches batched (M = 12800), fp16 MMA, BK=32
    conv_tc<0><<<dim3(100, 3), 256, conv_smem>>>(ft, wp1, b1, nullptr, (void*)t1);
    conv_tc<1><<<dim3(100, 3), 256, conv_smem>>>(t1, wp2, b2, ft, (void*)t2);
    // 7: LayerNorm + transpose to NCHW
    ln_k<<<dim3(200, 2), 256>>>(t2, lng, lnb, out);
}

// round 15
// speedup vs baseline: 1.0052x; 1.0052x over previous
#include <cuda_runtime.h>
#include <cuda_fp16.h>
#include <cstdint>

#define PP 6400
#define HH 80
#define WW 80
#define KC 256      // inner dim of correlation GEMM
#define CH 324      // real channels per direction
#define CP 384      // padded channel stride
#define CIE 352     // ci loop end (324 rounded up to 32)

#define GST 4       // gemm pipeline stages (BK=16)
#define CST 3       // conv pipeline stages (BK=32)
#define PADKG 24    // gemm smem row: 16 used + 8 pad halfs
#define STGHG 3072  // gemm halfs per stage per operand: 128 * PADKG
#define PADKC 40    // conv smem row: 32 used + 8 pad halfs
#define STGHC 5120  // conv halfs per stage per operand: 128 * PADKC

// ---------------- scratch (static device globals; no allocs) ----------------
__device__ __half g_corr0[(size_t)PP * PP];   // corr01  (P, 80, 80) fp16
__device__ __half g_corr1[(size_t)PP * PP];   // corr10 = corr01^T   fp16
__device__ __half g_f0h[PP * KC];             // fp16 f0, [p][k]
__device__ __half g_f1h[PP * KC];             // fp16 f1, [q][k]
__device__ __half g_feat[2 * PP * CP];        // lookup features (fp16), both branches
__device__ __half g_t1[2 * PP * CP];          // conv1 output (fp16)
__device__ float  g_t2[2 * PP * CP];          // conv2 output (fp32)
__device__ __half g_w1[9 * CP * CIE];         // [tap][co][ci] fp16
__device__ __half g_w2[9 * CP * CIE];

// ---------------- helpers ----------------
__device__ __forceinline__ void mma_f16(float4& c,
                                        uint32_t a0, uint32_t a1, uint32_t a2, uint32_t a3,
                                        uint32_t b0, uint32_t b1) {
    asm volatile(
        "mma.sync.aligned.m16n8k16.row.col.f32.f16.f16.f32 "
        "{%0,%1,%2,%3}, {%4,%5,%6,%7}, {%8,%9}, {%0,%1,%2,%3};"
        : "+f"(c.x), "+f"(c.y), "+f"(c.z), "+f"(c.w)
        : "r"(a0), "r"(a1), "r"(a2), "r"(a3), "r"(b0), "r"(b1));
}

__device__ __forceinline__ uint32_t ld32h(const __half* p) {
    return *(const uint32_t*)p;
}

__device__ __forceinline__ uint32_t su32(const void* p) {
    uint32_t a;
    asm("{ .reg .u64 t; cvta.to.shared.u64 t, %1; cvt.u32.u64 %0, t; }"
        : "=r"(a) : "l"(p));
    return a;
}

__device__ __forceinline__ void cpa16(uint32_t dst, const void* src, bool v) {
    asm volatile("cp.async.cg.shared.global [%0], [%1], 16, %2;"
                 :: "r"(dst), "l"(src), "r"(v ? 16 : 0));
}
__device__ __forceinline__ void cpa_commit() {
    asm volatile("cp.async.commit_group;");
}
template <int N>
__device__ __forceinline__ void cpa_wait() {
    asm volatile("cp.async.wait_group %0;" :: "n"(N));
}

// ---------------- transpose + fp16 convert: (KC, PP) -> [p][KC] half ----------------
__global__ void transh_k(const float* __restrict__ in, __half* __restrict__ out) {
    __shared__ float t[32][33];
    const int p0 = blockIdx.x * 32;
    const int k0 = blockIdx.y * 32;
    const int tx = threadIdx.x;
#pragma unroll
    for (int r = threadIdx.y; r < 32; r += 8)
        t[r][tx] = in[(size_t)(k0 + r) * PP + p0 + tx];
    __syncthreads();
#pragma unroll
    for (int r = threadIdx.y; r < 32; r += 8)
        out[(size_t)(p0 + r) * KC + k0 + tx] = __float2half(t[tx][r]);
}

// ---------------- weight repack: (3,3,324,324) HWIO -> [tap][co(384)][ci(352)] fp16 ----
__global__ void repack_w(const float* __restrict__ w1, const float* __restrict__ w2,
                         __half* __restrict__ wp1, __half* __restrict__ wp2) {
    const int id = blockIdx.x * blockDim.x + threadIdx.x;
    if (id >= 9 * CP * CIE) return;
    const float* w = blockIdx.y ? w2 : w1;
    __half* wp = blockIdx.y ? wp2 : wp1;
    const int ci = id % CIE;
    const int t = id / CIE;
    const int co = t % CP;
    const int tap = t / CP;
    const float v = (ci < CH && co < CH) ? w[((size_t)(tap * CH + ci)) * CH + co] : 0.f;
    wp[id] = __float2half(v);
}

// ---------------- fp16 tensor-core GEMM writing C and C^T (fp16 out, coalesced C1) ----
// A = f0h [p][KC], B = f1h [q][KC]. 128x128 tile, BK=16 (one k16 mma phase/slab),
// GST-stage cp.async pipeline. 8 warps (2x4), warp tile 64x32.
// C1 emitted via smem-staged transpose: 256B-contiguous rows.
__global__ __launch_bounds__(256) void gemm_tc(const __half* __restrict__ A,
                                               const __half* __restrict__ B,
                                               __half* __restrict__ C0,
                                               __half* __restrict__ C1) {
    extern __shared__ __align__(16) __half smh[];
    __half* Asb = smh;                      // GST stages of [128][PADKG]
    __half* Bsb = smh + GST * STGHG;
    const uint32_t asu = su32(Asb);
    const uint32_t bsu = su32(Bsb);

    const int tid = threadIdx.x;
    const int p0 = blockIdx.y * 128;
    const int q0 = blockIdx.x * 128;
    const int warp = tid >> 5, lane = tid & 31;
    const int wm = warp >> 2, wn = warp & 3;   // 2 x 4
    const int m0 = wm * 64, n0 = wn * 32;
    const int lr = lane >> 2, lc4 = lane & 3;
    const int arow = tid >> 1;              // loader row 0..127
    const int aseg = (tid & 1) * 8;         // halfs (16 B)

    float4 acc[4][4];
#pragma unroll
    for (int i = 0; i < 4; i++)
#pragma unroll
        for (int j = 0; j < 4; j++) acc[i][j] = make_float4(0.f, 0.f, 0.f, 0.f);

    const __half* Ap = A + (size_t)(p0 + arow) * KC + aseg;
    const __half* Bp = B + (size_t)(q0 + arow) * KC + aseg;
    const uint32_t adst = asu + (uint32_t)(arow * PADKG + aseg) * 2;
    const uint32_t bdst = bsu + (uint32_t)(arow * PADKG + aseg) * 2;

#define GEMM_ISSUE(SLAB, BUF)                                                      \
    do {                                                                           \
        const int koff = (SLAB) * 16;                                              \
        cpa16(adst + (BUF) * (STGHG * 2), Ap + koff, true);                        \
        cpa16(bdst + (BUF) * (STGHG * 2), Bp + koff, true);                        \
        cpa_commit();                                                              \
    } while (0)

    const int NSLAB = KC / 16;   // 16
#pragma unroll
    for (int s = 0; s < GST - 1; s++) GEMM_ISSUE(s, s);

    for (int it = 0; it < NSLAB; ++it) {
        cpa_wait<GST - 2>();
        __syncthreads();
        if (it + GST - 1 < NSLAB) GEMM_ISSUE(it + GST - 1, (it + GST - 1) % GST);
        const __half* Asf = Asb + (it % GST) * STGHG;
        const __half* Bsf = Bsb + (it % GST) * STGHG;
        uint32_t bf[4][2];
#pragma unroll
        for (int j = 0; j < 4; j++) {
            const int nb = n0 + j * 8 + lr;
            bf[j][0] = ld32h(Bsf + nb * PADKG + lc4 * 2);
            bf[j][1] = ld32h(Bsf + nb * PADKG + lc4 * 2 + 8);
        }
#pragma unroll
        for (int i = 0; i < 4; i++) {
            const int mb = m0 + i * 16 + lr;
            const uint32_t a0 = ld32h(Asf + mb * PADKG + lc4 * 2);
            const uint32_t a1 = ld32h(Asf + (mb + 8) * PADKG + lc4 * 2);
            const uint32_t a2 = ld32h(Asf + mb * PADKG + lc4 * 2 + 8);
            const uint32_t a3 = ld32h(Asf + (mb + 8) * PADKG + lc4 * 2 + 8);
#pragma unroll
            for (int j = 0; j < 4; j++)
                mma_f16(acc[i][j], a0, a1, a2, a3, bf[j][0], bf[j][1]);
        }
    }
#undef GEMM_ISSUE

    // C0: coalesced half2 stores straight from registers
#pragma unroll
    for (int i = 0; i < 4; i++) {
        const int r = p0 + m0 + i * 16 + lr;
#pragma unroll
        for (int j = 0; j < 4; j++) {
            const int c = q0 + n0 + j * 8 + lc4 * 2;
            *(__half2*)&C0[(size_t)r * PP + c] =
                __halves2half2(__float2half(acc[i][j].x), __float2half(acc[i][j].y));
            *(__half2*)&C0[(size_t)(r + 8) * PP + c] =
                __halves2half2(__float2half(acc[i][j].z), __float2half(acc[i][j].w));
        }
    }

    // C1: smem-staged transpose, two 64-column passes, 64B-contiguous per thread
    cpa_wait<0>();
    float* tile = (float*)smh;   // 64 x 132 floats = 33792 B (<= 49152 B pipeline smem)
#pragma unroll
    for (int pass = 0; pass < 2; pass++) {
        __syncthreads();
        if ((wn >> 1) == pass) {
            const int nloc = (wn & 1) * 32;
#pragma unroll
            for (int i = 0; i < 4; i++) {
                const int r = m0 + i * 16 + lr;
#pragma unroll
                for (int j = 0; j < 4; j++) {
                    const int cl = nloc + j * 8 + lc4 * 2;
                    tile[cl * 132 + r]           = acc[i][j].x;
                    tile[(cl + 1) * 132 + r]     = acc[i][j].y;
                    tile[cl * 132 + r + 8]       = acc[i][j].z;
                    tile[(cl + 1) * 132 + r + 8] = acc[i][j].w;
                }
            }
        }
        __syncthreads();
        const int cl2 = tid >> 2;          // 0..63 (C1 row within pass)
        const int sg = (tid & 3) * 32;     // 0,32,64,96 (p chunk)
        const float* srow = tile + cl2 * 132 + sg;
        __half2 hb[16];
#pragma unroll
        for (int u = 0; u < 16; u++)
            hb[u] = __floats2half2_rn(srow[2 * u], srow[2 * u + 1]);
        uint4* dst = (uint4*)&C1[(size_t)(q0 + pass * 64 + cl2) * PP + p0 + sg];
#pragma unroll
        for (int v = 0; v < 4; v++) dst[v] = ((const uint4*)hb)[v];
    }
}

// ---------------- fused pyramid + lookup (fp16 corr input, fp32 math, fp16 out) -------
__global__ __launch_bounds__(256) void pyrlook_k(const __half* __restrict__ corr0,
                                                 const __half* __restrict__ corr1,
                                                 __half* __restrict__ feat) {
    __shared__ float L1[1600];
    __shared__ float L2[400];
    __shared__ float L3[100];
    const int p = blockIdx.x;
    const int br = blockIdx.y;
    const __half* row = (br ? corr1 : corr0) + (size_t)p * PP;

    for (int i = threadIdx.x; i < 1600; i += 256) {
        const int y = i / 40, x = i % 40;
        const float2 a = __half22float2(*(const __half2*)(row + y * 160 + x * 2));
        const float2 b = __half22float2(*(const __half2*)(row + y * 160 + 80 + x * 2));
        L1[i] = 0.25f * (a.x + a.y + b.x + b.y);
    }
    __syncthreads();
    for (int i = threadIdx.x; i < 400; i += 256) {
        const int y = i / 20, x = i % 20;
        const float* m = L1 + y * 80 + x * 2;
        L2[i] = 0.25f * (m[0] + m[1] + m[40] + m[41]);
    }
    __syncthreads();
    for (int i = threadIdx.x; i < 100; i += 256) {
        const int y = i / 10, x = i % 10;
        const float* m = L2 + y * 40 + x * 2;
        L3[i] = 0.25f * (m[0] + m[1] + m[20] + m[21]);
    }
    __syncthreads();

    const int px = p % WW, py = p / WW;
    __half* out = feat + ((size_t)br * PP + p) * CP;
    for (int ch = threadIdx.x; ch < CP; ch += 256) {
        float v = 0.f;
        if (ch < 81) {
            const int dx = ch / 9 - 4;
            const int dy = ch % 9 - 4;
            const int ix = px + dx, iy = py + dy;
            if (((unsigned)ix < (unsigned)WW) && ((unsigned)iy < (unsigned)HH))
                v = __half2float(row[iy * WW + ix]);
        } else if (ch < CH) {
            const int lvl = ch / 81;
            const int off = ch % 81;
            const int dx = off / 9 - 4;
            const int dy = off % 9 - 4;
            const float* base;
            int hl;
            switch (lvl) {
                case 1: base = L1; hl = 40; break;
                case 2: base = L2; hl = 20; break;
                default: base = L3; hl = 10; break;
            }
            const int wl = hl;
            const float s = (float)(1 << lvl);
            const float cx = (2.f * px + 1.f) / (2.f * s) - 0.5f + (float)dx;
            const float cy = (2.f * py + 1.f) / (2.f * s) - 0.5f + (float)dy;
            const float x0f = floorf(cx), y0f = floorf(cy);
            const int ix = (int)x0f, iy = (int)y0f;
            const float fx = cx - x0f, fy = cy - y0f;
            float v00 = 0.f, v10 = 0.f, v01 = 0.f, v11 = 0.f;
            const bool xv0 = (ix >= 0) & (ix < wl);
            const bool xv1 = (ix + 1 >= 0) & (ix + 1 < wl);
            const bool yv0 = (iy >= 0) & (iy < hl);
            const bool yv1 = (iy + 1 >= 0) & (iy + 1 < hl);
            if (yv0) {
                if (xv0) v00 = base[iy * wl + ix];
                if (xv1) v10 = base[iy * wl + ix + 1];
            }
            if (yv1) {
                if (xv0) v01 = base[(iy + 1) * wl + ix];
                if (xv1) v11 = base[(iy + 1) * wl + ix + 1];
            }
            v = v00 * (1.f - fx) * (1.f - fy) + v10 * fx * (1.f - fy)
              + v01 * (1.f - fx) * fy + v11 * fx * fy;
        }
        out[ch] = __float2half(v);
    }
}

// ---------------- 3x3 conv as implicit GEMM (fp16), BK=32, CST-stage pipeline ---------
// M=12800 (BM=128), N=384 (BN=128), K=9 taps x 352, BK=32 (two k16 phases/slab).
// 8 warps (2x4), warp tile 64x32. Epilogue relu(acc+bias) [+res].
template <int ADD_RES>
__global__ __launch_bounds__(256, 2) void conv_tc(const __half* __restrict__ X,
                                                  const __half* __restrict__ Wt,
                                                  const float* __restrict__ bias,
                                                  const __half* __restrict__ res,
                                                  void* __restrict__ Yout) {
    extern __shared__ __align__(16) __half smh[];
    __half* Asb = smh;                      // CST stages of [128][PADKC]
    __half* Bsb = smh + CST * STGHC;
    const uint32_t asu = su32(Asb);
    const uint32_t bsu = su32(Bsb);

    const int tid = threadIdx.x;
    const int p0 = blockIdx.x * 128;
    const int c0 = blockIdx.y * 128;
    const int warp = tid >> 5, lane = tid & 31;
    const int wm = warp >> 2, wn = warp & 3;   // 2 x 4
    const int m0 = wm * 64, n0 = wn * 32;
    const int lr = lane >> 2, lc4 = lane & 3;

    const int arow = tid >> 1;              // loader row 0..127
    const int aseg = (tid & 1) * 16;        // halfs
    const int pl = (p0 + arow) % PP;
    const int apy = pl / WW, apx = pl % WW;

    const uint32_t adst = asu + (uint32_t)(arow * PADKC + aseg) * 2;
    const uint32_t bdst = bsu + (uint32_t)(arow * PADKC + aseg) * 2;
    const __half* Xr = X + (size_t)(p0 + arow) * CP + aseg;
    const __half* Wr = Wt + (size_t)(c0 + arow) * CIE + aseg;

    float4 acc[4][4];
#pragma unroll
    for (int i = 0; i < 4; i++)
#pragma unroll
        for (int j = 0; j < 4; j++) acc[i][j] = make_float4(0.f, 0.f, 0.f, 0.f);

#define CONV_ISSUE(SLAB, BUF)                                                        \
    do {                                                                             \
        const int tap_ = (SLAB) / 11;                                                \
        const int kb_ = ((SLAB) % 11) * 32;                                          \
        const int dy = tap_ / 3 - 1, dx = tap_ % 3 - 1;                              \
        const bool valid = ((unsigned)(apy + dy) < (unsigned)HH) &&                  \
                           ((unsigned)(apx + dx) < (unsigned)WW);                    \
        const __half* xs = Xr + (size_t)(dy * WW + dx) * CP + kb_;                   \
        cpa16(adst + (BUF) * (STGHC * 2), xs, valid);                                \
        cpa16(adst + (BUF) * (STGHC * 2) + 16, xs + 8, valid);                       \
        const __half* ws = Wr + (size_t)tap_ * (CP * CIE) + kb_;                     \
        cpa16(bdst + (BUF) * (STGHC * 2), ws, true);                                 \
        cpa16(bdst + (BUF) * (STGHC * 2) + 16, ws + 8, true);                        \
        cpa_commit();                                                                \
    } while (0)

    const int NIT = 9 * 11;   // 99
#pragma unroll
    for (int s = 0; s < CST - 1; s++) CONV_ISSUE(s, s);

    for (int it = 0; it < NIT; ++it) {
        cpa_wait<CST - 2>();
        __syncthreads();
        if (it + CST - 1 < NIT) CONV_ISSUE(it + CST - 1, (it + CST - 1) % CST);
        const __half* Asf = Asb + (it % CST) * STGHC;
        const __half* Bsf = Bsb + (it % CST) * STGHC;
#pragma unroll
        for (int ks = 0; ks < 32; ks += 16) {
            uint32_t bf[4][2];
#pragma unroll
            for (int j = 0; j < 4; j++) {
                const int nb = n0 + j * 8 + lr;
                bf[j][0] = ld32h(Bsf + nb * PADKC + ks + lc4 * 2);
                bf[j][1] = ld32h(Bsf + nb * PADKC + ks + lc4 * 2 + 8);
            }
#pragma unroll
            for (int i = 0; i < 4; i++) {
                const int mb = m0 + i * 16 + lr;
                const uint32_t a0 = ld32h(Asf + mb * PADKC + ks + lc4 * 2);
                const uint32_t a1 = ld32h(Asf + (mb + 8) * PADKC + ks + lc4 * 2);
                const uint32_t a2 = ld32h(Asf + mb * PADKC + ks + lc4 * 2 + 8);
                const uint32_t a3 = ld32h(Asf + (mb + 8) * PADKC + ks + lc4 * 2 + 8);
#pragma unroll
                for (int j = 0; j < 4; j++)
                    mma_f16(acc[i][j], a0, a1, a2, a3, bf[j][0], bf[j][1]);
            }
        }
    }
#undef CONV_ISSUE

#pragma unroll
    for (int i = 0; i < 4; i++) {
        const int r0 = p0 + m0 + i * 16 + lr;
#pragma unroll
        for (int j = 0; j < 4; j++) {
            const int c = c0 + n0 + j * 8 + lc4 * 2;
            const float bv0 = (c < CH) ? bias[c] : 0.f;
            const float bv1 = (c + 1 < CH) ? bias[c + 1] : 0.f;
            float vx = fmaxf(acc[i][j].x + bv0, 0.f);
            float vy = fmaxf(acc[i][j].y + bv1, 0.f);
            float vz = fmaxf(acc[i][j].z + bv0, 0.f);
            float vw = fmaxf(acc[i][j].w + bv1, 0.f);
            if (ADD_RES) {
                const float2 r0v = __half22float2(*(const __half2*)&res[(size_t)r0 * CP + c]);
                const float2 r1v = __half22float2(*(const __half2*)&res[(size_t)(r0 + 8) * CP + c]);
                float* Yf = (float*)Yout;
                *(float2*)&Yf[(size_t)r0 * CP + c]       = make_float2(vx + r0v.x, vy + r0v.y);
                *(float2*)&Yf[(size_t)(r0 + 8) * CP + c] = make_float2(vz + r1v.x, vw + r1v.y);
            } else {
                __half* Yh = (__half*)Yout;
                *(__half2*)&Yh[(size_t)r0 * CP + c]       = __floats2half2_rn(vx, vy);
                *(__half2*)&Yh[(size_t)(r0 + 8) * CP + c] = __floats2half2_rn(vz, vw);
            }
        }
    }
}

// ---------------- LayerNorm over 324 channels + NHWC -> NCHW store (both branches) ----
__global__ __launch_bounds__(256) void ln_k(const float* __restrict__ Yin,
                                            const float* __restrict__ g,
                                            const float* __restrict__ bta,
                                            float* __restrict__ out) {
    __shared__ float tile[CH][33];
    const int br = blockIdx.y;
    const int p0 = blockIdx.x * 32;
    const float* Ybr = Yin + (size_t)br * PP * CP;
    const int cbase = br * CH;
    const int warp = threadIdx.x >> 5, lane = threadIdx.x & 31;
#pragma unroll
    for (int r = 0; r < 4; r++) {
        const int lp = warp + r * 8;
        const float* row = Ybr + (size_t)(p0 + lp) * CP;
        float vals[11];
        float s = 0.f, sq = 0.f;
#pragma unroll
        for (int j = 0; j < 11; j++) {
            const int ch = lane + j * 32;
            float v = (ch < CH) ? row[ch] : 0.f;
            vals[j] = v;
            s += v;
            sq += v * v;
        }
#pragma unroll
        for (int o = 16; o; o >>= 1) {
            s += __shfl_xor_sync(0xffffffffu, s, o);
            sq += __shfl_xor_sync(0xffffffffu, sq, o);
        }
        const float mean = s * (1.f / 324.f);
        const float var = sq * (1.f / 324.f) - mean * mean;
        const float inv = rsqrtf(var + 1e-5f);
#pragma unroll
        for (int j = 0; j < 11; j++) {
            const int ch = lane + j * 32;
            if (ch < CH)
                tile[ch][lp] = (vals[j] - mean) * inv * g[ch] + bta[ch];
        }
    }
    __syncthreads();
    const int col = threadIdx.x & 31;
    for (int ch = threadIdx.x >> 5; ch < CH; ch += 8)
        out[(size_t)(cbase + ch) * PP + p0 + col] = tile[ch][col];
}

// ---------------- launch ----------------
extern "C" void kernel_launch(void* const* d_in, const int* in_sizes, int n_in,
                              void* d_out, int out_size) {
    const float* f0  = (const float*)d_in[0];
    const float* f1  = (const float*)d_in[1];
    const float* w1  = (const float*)d_in[2];
    const float* b1  = (const float*)d_in[3];
    const float* w2  = (const float*)d_in[4];
    const float* b2  = (const float*)d_in[5];
    const float* lng = (const float*)d_in[6];
    const float* lnb = (const float*)d_in[7];
    float* out = (float*)d_out;

    float *t2;
    __half *corr0, *corr1, *f0h, *f1h, *ft, *t1, *wp1, *wp2;
    cudaGetSymbolAddress((void**)&corr0, g_corr0);
    cudaGetSymbolAddress((void**)&corr1, g_corr1);
    cudaGetSymbolAddress((void**)&f0h, g_f0h);
    cudaGetSymbolAddress((void**)&f1h, g_f1h);
    cudaGetSymbolAddress((void**)&ft, g_feat);
    cudaGetSymbolAddress((void**)&t1, g_t1);
    cudaGetSymbolAddress((void**)&t2, g_t2);
    cudaGetSymbolAddress((void**)&wp1, g_w1);
    cudaGetSymbolAddress((void**)&wp2, g_w2);

    const int gemm_smem = GST * STGHG * 2 * 2;   // 49152 B (>= 33792 B epilogue tile)
    const int conv_smem = CST * STGHC * 2 * 2;   // 61440 B
    cudaFuncSetAttribute(gemm_tc, cudaFuncAttributeMaxDynamicSharedMemorySize, gemm_smem);
    cudaFuncSetAttribute(conv_tc<0>, cudaFuncAttributeMaxDynamicSharedMemorySize, conv_smem);
    cudaFuncSetAttribute(conv_tc<1>, cudaFuncAttributeMaxDynamicSharedMemorySize, conv_smem);

    // 0,1: transpose + fp16 convert of f0/f1 -> [p][k]
    transh_k<<<dim3(200, 8), dim3(32, 8)>>>(f0, f0h);
    transh_k<<<dim3(200, 8), dim3(32, 8)>>>(f1, f1h);
    // 2: weight repack (both sets) -> [tap][co][ci] fp16
    repack_w<<<dim3((9 * CP * CIE + 255) / 256, 2), 256>>>(w1, w2, wp1, wp2);
    // 3: correlation GEMM (fp16 MMA) writing corr01 and corr10 (fp16, coalesced)
    gemm_tc<<<dim3(50, 50), 256, gemm_smem>>>(f0h, f1h, corr0, corr1);
    // 4: fused pyramid + lookup (both branches, fp16 corr in, fp16 feat out)
    pyrlook_k<<<dim3(PP, 2), 256>>>(corr0, corr1, ft);
    // 5,6: convs, both branches batched (M = 12800), fp16 MMA, BK=32
    conv_tc<0><<<dim3(100, 3), 256, conv_smem>>>(ft, wp1, b1, nullptr, (void*)t1);
    conv_tc<1><<<dim3(100, 3), 256, conv_smem>>>(t1, wp2, b2, ft, (void*)t2);
    // 7: LayerNorm + transpose to NCHW
    ln_k<<<dim3(200, 2), 256>>>(t2, lng, lnb, out);
}

// round 16
// speedup vs baseline: 1.1117x; 1.1060x over previous
#include <cuda_runtime.h>
#include <cuda_fp16.h>
#include <cstdint>

#define PP 6400
#define HH 80
#define WW 80
#define KC 256      // inner dim of correlation GEMM
#define CH 324      // real channels per direction
#define CP 384      // padded channel stride
#define CIE 352     // ci loop end (324 rounded up to 32)

#define GST 4       // gemm pipeline stages (BK=16)
#define CST 3       // conv pipeline stages (BK=32)
#define PADKG 24    // gemm smem row: 16 used + 8 pad halfs (48B stride, ldsm conflict-free)
#define STGHG 3072  // gemm halfs per stage per operand: 128 * PADKG
#define PADKC 40    // conv smem row: 32 used + 8 pad halfs (80B stride, ldsm conflict-free)
#define STGHC 5120  // conv halfs per stage per operand: 128 * PADKC

// ---------------- scratch (static device globals; no allocs) ----------------
__device__ __half g_corr0[(size_t)PP * PP];   // corr01  (P, 80, 80) fp16
__device__ __half g_corr1[(size_t)PP * PP];   // corr10 = corr01^T   fp16
__device__ __half g_f0h[PP * KC];             // fp16 f0, [p][k]
__device__ __half g_f1h[PP * KC];             // fp16 f1, [q][k]
__device__ __half g_feat[2 * PP * CP];        // lookup features (fp16), both branches
__device__ __half g_t1[2 * PP * CP];          // conv1 output (fp16)
__device__ float  g_t2[2 * PP * CP];          // conv2 output (fp32)
__device__ __half g_w1[9 * CP * CIE];         // [tap][co][ci] fp16
__device__ __half g_w2[9 * CP * CIE];

// ---------------- helpers ----------------
__device__ __forceinline__ void mma_f16(float4& c,
                                        uint32_t a0, uint32_t a1, uint32_t a2, uint32_t a3,
                                        uint32_t b0, uint32_t b1) {
    asm volatile(
        "mma.sync.aligned.m16n8k16.row.col.f32.f16.f16.f32 "
        "{%0,%1,%2,%3}, {%4,%5,%6,%7}, {%8,%9}, {%0,%1,%2,%3};"
        : "+f"(c.x), "+f"(c.y), "+f"(c.z), "+f"(c.w)
        : "r"(a0), "r"(a1), "r"(a2), "r"(a3), "r"(b0), "r"(b1));
}

__device__ __forceinline__ void ldsm4(uint32_t* r, uint32_t addr) {
    asm volatile("ldmatrix.sync.aligned.m8n8.x4.shared.b16 {%0,%1,%2,%3}, [%4];"
                 : "=r"(r[0]), "=r"(r[1]), "=r"(r[2]), "=r"(r[3]) : "r"(addr));
}

__device__ __forceinline__ uint32_t su32(const void* p) {
    uint32_t a;
    asm("{ .reg .u64 t; cvta.to.shared.u64 t, %1; cvt.u32.u64 %0, t; }"
        : "=r"(a) : "l"(p));
    return a;
}

__device__ __forceinline__ void cpa16(uint32_t dst, const void* src, bool v) {
    asm volatile("cp.async.cg.shared.global [%0], [%1], 16, %2;"
                 :: "r"(dst), "l"(src), "r"(v ? 16 : 0));
}
__device__ __forceinline__ void cpa_commit() {
    asm volatile("cp.async.commit_group;");
}
template <int N>
__device__ __forceinline__ void cpa_wait() {
    asm volatile("cp.async.wait_group %0;" :: "n"(N));
}

// ---------------- transpose + fp16 convert: (KC, PP) -> [p][KC] half ----------------
__global__ void transh_k(const float* __restrict__ in, __half* __restrict__ out) {
    __shared__ float t[32][33];
    const int p0 = blockIdx.x * 32;
    const int k0 = blockIdx.y * 32;
    const int tx = threadIdx.x;
#pragma unroll
    for (int r = threadIdx.y; r < 32; r += 8)
        t[r][tx] = in[(size_t)(k0 + r) * PP + p0 + tx];
    __syncthreads();
#pragma unroll
    for (int r = threadIdx.y; r < 32; r += 8)
        out[(size_t)(p0 + r) * KC + k0 + tx] = __float2half(t[tx][r]);
}

// ---------------- weight repack: (3,3,324,324) HWIO -> [tap][co(384)][ci(352)] fp16 ----
__global__ void repack_w(const float* __restrict__ w1, const float* __restrict__ w2,
                         __half* __restrict__ wp1, __half* __restrict__ wp2) {
    const int id = blockIdx.x * blockDim.x + threadIdx.x;
    if (id >= 9 * CP * CIE) return;
    const float* w = blockIdx.y ? w2 : w1;
    __half* wp = blockIdx.y ? wp2 : wp1;
    const int ci = id % CIE;
    const int t = id / CIE;
    const int co = t % CP;
    const int tap = t / CP;
    const float v = (ci < CH && co < CH) ? w[((size_t)(tap * CH + ci)) * CH + co] : 0.f;
    wp[id] = __float2half(v);
}

// ---------------- fp16 tensor-core GEMM writing C and C^T (ldmatrix fragments) --------
// A = f0h [p][KC], B = f1h [q][KC]. 128x128 tile, BK=16, GST-stage cp.async pipeline.
// 8 warps (2x4), warp tile 64x32. C1 via smem-staged transpose (coalesced).
__global__ __launch_bounds__(256) void gemm_tc(const __half* __restrict__ A,
                                               const __half* __restrict__ B,
                                               __half* __restrict__ C0,
                                               __half* __restrict__ C1) {
    extern __shared__ __align__(16) __half smh[];
    __half* Asb = smh;                      // GST stages of [128][PADKG]
    __half* Bsb = smh + GST * STGHG;
    const uint32_t asu = su32(Asb);
    const uint32_t bsu = su32(Bsb);

    const int tid = threadIdx.x;
    const int p0 = blockIdx.y * 128;
    const int q0 = blockIdx.x * 128;
    const int warp = tid >> 5, lane = tid & 31;
    const int wm = warp >> 2, wn = warp & 3;   // 2 x 4
    const int m0 = wm * 64, n0 = wn * 32;
    const int lr = lane >> 2, lc4 = lane & 3;
    const int arow = tid >> 1;              // loader row 0..127
    const int aseg = (tid & 1) * 8;         // halfs (16 B)

    // ldmatrix per-lane byte offsets within a stage
    const uint32_t aoff = (uint32_t)(((m0 + (lane & 7) + ((lane >> 3) & 1) * 8) * PADKG
                                      + ((lane >> 4) & 1) * 8) * 2);
    const uint32_t boff = (uint32_t)(((n0 + (lane & 7) + ((lane >> 4) & 1) * 8) * PADKG
                                      + ((lane >> 3) & 1) * 8) * 2);

    float4 acc[4][4];
#pragma unroll
    for (int i = 0; i < 4; i++)
#pragma unroll
        for (int j = 0; j < 4; j++) acc[i][j] = make_float4(0.f, 0.f, 0.f, 0.f);

    const __half* Ap = A + (size_t)(p0 + arow) * KC + aseg;
    const __half* Bp = B + (size_t)(q0 + arow) * KC + aseg;
    const uint32_t adst = asu + (uint32_t)(arow * PADKG + aseg) * 2;
    const uint32_t bdst = bsu + (uint32_t)(arow * PADKG + aseg) * 2;

#define GEMM_ISSUE(SLAB, BUF)                                                      \
    do {                                                                           \
        const int koff = (SLAB) * 16;                                              \
        cpa16(adst + (BUF) * (STGHG * 2), Ap + koff, true);                        \
        cpa16(bdst + (BUF) * (STGHG * 2), Bp + koff, true);                        \
        cpa_commit();                                                              \
    } while (0)

    const int NSLAB = KC / 16;   // 16
#pragma unroll
    for (int s = 0; s < GST - 1; s++) GEMM_ISSUE(s, s);

    for (int it = 0; it < NSLAB; ++it) {
        cpa_wait<GST - 2>();
        __syncthreads();
        if (it + GST - 1 < NSLAB) GEMM_ISSUE(it + GST - 1, (it + GST - 1) % GST);
        const uint32_t asf = asu + (it % GST) * (STGHG * 2);
        const uint32_t bsf = bsu + (it % GST) * (STGHG * 2);
        uint32_t bf01[4], bf23[4];
        ldsm4(bf01, bsf + boff);                               // n-tiles 0,1
        ldsm4(bf23, bsf + boff + 16 * PADKG * 2);              // n-tiles 2,3
#pragma unroll
        for (int i = 0; i < 4; i++) {
            uint32_t af[4];
            ldsm4(af, asf + aoff + (uint32_t)(i * 16 * PADKG * 2));
            mma_f16(acc[i][0], af[0], af[1], af[2], af[3], bf01[0], bf01[1]);
            mma_f16(acc[i][1], af[0], af[1], af[2], af[3], bf01[2], bf01[3]);
            mma_f16(acc[i][2], af[0], af[1], af[2], af[3], bf23[0], bf23[1]);
            mma_f16(acc[i][3], af[0], af[1], af[2], af[3], bf23[2], bf23[3]);
        }
    }
#undef GEMM_ISSUE

    // C0: coalesced half2 stores straight from registers
#pragma unroll
    for (int i = 0; i < 4; i++) {
        const int r = p0 + m0 + i * 16 + lr;
#pragma unroll
        for (int j = 0; j < 4; j++) {
            const int c = q0 + n0 + j * 8 + lc4 * 2;
            *(__half2*)&C0[(size_t)r * PP + c] =
                __halves2half2(__float2half(acc[i][j].x), __float2half(acc[i][j].y));
            *(__half2*)&C0[(size_t)(r + 8) * PP + c] =
                __halves2half2(__float2half(acc[i][j].z), __float2half(acc[i][j].w));
        }
    }

    // C1: smem-staged transpose, two 64-column passes, 64B-contiguous per thread
    cpa_wait<0>();
    float* tile = (float*)smh;   // 64 x 132 floats = 33792 B
#pragma unroll
    for (int pass = 0; pass < 2; pass++) {
        __syncthreads();
        if ((wn >> 1) == pass) {
            const int nloc = (wn & 1) * 32;
#pragma unroll
            for (int i = 0; i < 4; i++) {
                const int r = m0 + i * 16 + lr;
#pragma unroll
                for (int j = 0; j < 4; j++) {
                    const int cl = nloc + j * 8 + lc4 * 2;
                    tile[cl * 132 + r]           = acc[i][j].x;
                    tile[(cl + 1) * 132 + r]     = acc[i][j].y;
                    tile[cl * 132 + r + 8]       = acc[i][j].z;
                    tile[(cl + 1) * 132 + r + 8] = acc[i][j].w;
                }
            }
        }
        __syncthreads();
        const int cl2 = tid >> 2;          // 0..63 (C1 row within pass)
        const int sg = (tid & 3) * 32;     // 0,32,64,96 (p chunk)
        const float* srow = tile + cl2 * 132 + sg;
        __half2 hb[16];
#pragma unroll
        for (int u = 0; u < 16; u++)
            hb[u] = __floats2half2_rn(srow[2 * u], srow[2 * u + 1]);
        uint4* dst = (uint4*)&C1[(size_t)(q0 + pass * 64 + cl2) * PP + p0 + sg];
#pragma unroll
        for (int v = 0; v < 4; v++) dst[v] = ((const uint4*)hb)[v];
    }
}

// ---------------- fused pyramid + lookup (fp16 corr input, fp32 math, fp16 out) -------
__global__ __launch_bounds__(256) void pyrlook_k(const __half* __restrict__ corr0,
                                                 const __half* __restrict__ corr1,
                                                 __half* __restrict__ feat) {
    __shared__ float L1[1600];
    __shared__ float L2[400];
    __shared__ float L3[100];
    const int p = blockIdx.x;
    const int br = blockIdx.y;
    const __half* row = (br ? corr1 : corr0) + (size_t)p * PP;

    for (int i = threadIdx.x; i < 1600; i += 256) {
        const int y = i / 40, x = i % 40;
        const float2 a = __half22float2(*(const __half2*)(row + y * 160 + x * 2));
        const float2 b = __half22float2(*(const __half2*)(row + y * 160 + 80 + x * 2));
        L1[i] = 0.25f * (a.x + a.y + b.x + b.y);
    }
    __syncthreads();
    for (int i = threadIdx.x; i < 400; i += 256) {
        const int y = i / 20, x = i % 20;
        const float* m = L1 + y * 80 + x * 2;
        L2[i] = 0.25f * (m[0] + m[1] + m[40] + m[41]);
    }
    __syncthreads();
    for (int i = threadIdx.x; i < 100; i += 256) {
        const int y = i / 10, x = i % 10;
        const float* m = L2 + y * 40 + x * 2;
        L3[i] = 0.25f * (m[0] + m[1] + m[20] + m[21]);
    }
    __syncthreads();

    const int px = p % WW, py = p / WW;
    __half* out = feat + ((size_t)br * PP + p) * CP;
    for (int ch = threadIdx.x; ch < CP; ch += 256) {
        float v = 0.f;
        if (ch < 81) {
            const int dx = ch / 9 - 4;
            const int dy = ch % 9 - 4;
            const int ix = px + dx, iy = py + dy;
            if (((unsigned)ix < (unsigned)WW) && ((unsigned)iy < (unsigned)HH))
                v = __half2float(row[iy * WW + ix]);
        } else if (ch < CH) {
            const int lvl = ch / 81;
            const int off = ch % 81;
            const int dx = off / 9 - 4;
            const int dy = off % 9 - 4;
            const float* base;
            int hl;
            switch (lvl) {
                case 1: base = L1; hl = 40; break;
                case 2: base = L2; hl = 20; break;
                default: base = L3; hl = 10; break;
            }
            const int wl = hl;
            const float s = (float)(1 << lvl);
            const float cx = (2.f * px + 1.f) / (2.f * s) - 0.5f + (float)dx;
            const float cy = (2.f * py + 1.f) / (2.f * s) - 0.5f + (float)dy;
            const float x0f = floorf(cx), y0f = floorf(cy);
            const int ix = (int)x0f, iy = (int)y0f;
            const float fx = cx - x0f, fy = cy - y0f;
            float v00 = 0.f, v10 = 0.f, v01 = 0.f, v11 = 0.f;
            const bool xv0 = (ix >= 0) & (ix < wl);
            const bool xv1 = (ix + 1 >= 0) & (ix + 1 < wl);
            const bool yv0 = (iy >= 0) & (iy < hl);
            const bool yv1 = (iy + 1 >= 0) & (iy + 1 < hl);
            if (yv0) {
                if (xv0) v00 = base[iy * wl + ix];
                if (xv1) v10 = base[iy * wl + ix + 1];
            }
            if (yv1) {
                if (xv0) v01 = base[(iy + 1) * wl + ix];
                if (xv1) v11 = base[(iy + 1) * wl + ix + 1];
            }
            v = v00 * (1.f - fx) * (1.f - fy) + v10 * fx * (1.f - fy)
              + v01 * (1.f - fx) * fy + v11 * fx * fy;
        }
        out[ch] = __float2half(v);
    }
}

// ---------------- 3x3 conv as implicit GEMM (fp16, ldmatrix), BK=32, CST stages -------
// M=12800 (BM=128), N=384 (BN=128), K=9 taps x 352, BK=32 (two k16 phases/slab).
// 8 warps (2x4), warp tile 64x32. Epilogue relu(acc+bias) [+res].
template <int ADD_RES>
__global__ __launch_bounds__(256, 2) void conv_tc(const __half* __restrict__ X,
                                                  const __half* __restrict__ Wt,
                                                  const float* __restrict__ bias,
                                                  const __half* __restrict__ res,
                                                  void* __restrict__ Yout) {
    extern __shared__ __align__(16) __half smh[];
    __half* Asb = smh;                      // CST stages of [128][PADKC]
    __half* Bsb = smh + CST * STGHC;
    const uint32_t asu = su32(Asb);
    const uint32_t bsu = su32(Bsb);

    const int tid = threadIdx.x;
    const int p0 = blockIdx.x * 128;
    const int c0 = blockIdx.y * 128;
    const int warp = tid >> 5, lane = tid & 31;
    const int wm = warp >> 2, wn = warp & 3;   // 2 x 4
    const int m0 = wm * 64, n0 = wn * 32;
    const int lr = lane >> 2, lc4 = lane & 3;

    const uint32_t aoff = (uint32_t)(((m0 + (lane & 7) + ((lane >> 3) & 1) * 8) * PADKC
                                      + ((lane >> 4) & 1) * 8) * 2);
    const uint32_t boff = (uint32_t)(((n0 + (lane & 7) + ((lane >> 4) & 1) * 8) * PADKC
                                      + ((lane >> 3) & 1) * 8) * 2);

    const int arow = tid >> 1;              // loader row 0..127
    const int aseg = (tid & 1) * 16;        // halfs
    const int pl = (p0 + arow) % PP;
    const int apy = pl / WW, apx = pl % WW;

    const uint32_t adst = asu + (uint32_t)(arow * PADKC + aseg) * 2;
    const uint32_t bdst = bsu + (uint32_t)(arow * PADKC + aseg) * 2;
    const __half* Xr = X + (size_t)(p0 + arow) * CP + aseg;
    const __half* Wr = Wt + (size_t)(c0 + arow) * CIE + aseg;

    float4 acc[4][4];
#pragma unroll
    for (int i = 0; i < 4; i++)
#pragma unroll
        for (int j = 0; j < 4; j++) acc[i][j] = make_float4(0.f, 0.f, 0.f, 0.f);

#define CONV_ISSUE(SLAB, BUF)                                                        \
    do {                                                                             \
        const int tap_ = (SLAB) / 11;                                                \
        const int kb_ = ((SLAB) % 11) * 32;                                          \
        const int dy = tap_ / 3 - 1, dx = tap_ % 3 - 1;                              \
        const bool valid = ((unsigned)(apy + dy) < (unsigned)HH) &&                  \
                           ((unsigned)(apx + dx) < (unsigned)WW);                    \
        const __half* xs = Xr + (size_t)(dy * WW + dx) * CP + kb_;                   \
        cpa16(adst + (BUF) * (STGHC * 2), xs, valid);                                \
        cpa16(adst + (BUF) * (STGHC * 2) + 16, xs + 8, valid);                       \
        const __half* ws = Wr + (size_t)tap_ * (CP * CIE) + kb_;                     \
        cpa16(bdst + (BUF) * (STGHC * 2), ws, true);                                 \
        cpa16(bdst + (BUF) * (STGHC * 2) + 16, ws + 8, true);                        \
        cpa_commit();                                                                \
    } while (0)

    const int NIT = 9 * 11;   // 99
#pragma unroll
    for (int s = 0; s < CST - 1; s++) CONV_ISSUE(s, s);

    for (int it = 0; it < NIT; ++it) {
        cpa_wait<CST - 2>();
        __syncthreads();
        if (it + CST - 1 < NIT) CONV_ISSUE(it + CST - 1, (it + CST - 1) % CST);
        const uint32_t asf = asu + (it % CST) * (STGHC * 2);
        const uint32_t bsf = bsu + (it % CST) * (STGHC * 2);
#pragma unroll
        for (int ks = 0; ks < 32; ks += 16) {
            uint32_t bf01[4], bf23[4];
            ldsm4(bf01, bsf + boff + ks * 2);
            ldsm4(bf23, bsf + boff + ks * 2 + 16 * PADKC * 2);
#pragma unroll
            for (int i = 0; i < 4; i++) {
                uint32_t af[4];
                ldsm4(af, asf + aoff + ks * 2 + (uint32_t)(i * 16 * PADKC * 2));
                mma_f16(acc[i][0], af[0], af[1], af[2], af[3], bf01[0], bf01[1]);
                mma_f16(acc[i][1], af[0], af[1], af[2], af[3], bf01[2], bf01[3]);
                mma_f16(acc[i][2], af[0], af[1], af[2], af[3], bf23[0], bf23[1]);
                mma_f16(acc[i][3], af[0], af[1], af[2], af[3], bf23[2], bf23[3]);
            }
        }
    }
#undef CONV_ISSUE

#pragma unroll
    for (int i = 0; i < 4; i++) {
        const int r0 = p0 + m0 + i * 16 + lr;
#pragma unroll
        for (int j = 0; j < 4; j++) {
            const int c = c0 + n0 + j * 8 + lc4 * 2;
            const float bv0 = (c < CH) ? bias[c] : 0.f;
            const float bv1 = (c + 1 < CH) ? bias[c + 1] : 0.f;
            float vx = fmaxf(acc[i][j].x + bv0, 0.f);
            float vy = fmaxf(acc[i][j].y + bv1, 0.f);
            float vz = fmaxf(acc[i][j].z + bv0, 0.f);
            float vw = fmaxf(acc[i][j].w + bv1, 0.f);
            if (ADD_RES) {
                const float2 r0v = __half22float2(*(const __half2*)&res[(size_t)r0 * CP + c]);
                const float2 r1v = __half22float2(*(const __half2*)&res[(size_t)(r0 + 8) * CP + c]);
                float* Yf = (float*)Yout;
                *(float2*)&Yf[(size_t)r0 * CP + c]       = make_float2(vx + r0v.x, vy + r0v.y);
                *(float2*)&Yf[(size_t)(r0 + 8) * CP + c] = make_float2(vz + r1v.x, vw + r1v.y);
            } else {
                __half* Yh = (__half*)Yout;
                *(__half2*)&Yh[(size_t)r0 * CP + c]       = __floats2half2_rn(vx, vy);
                *(__half2*)&Yh[(size_t)(r0 + 8) * CP + c] = __floats2half2_rn(vz, vw);
            }
        }
    }
}

// ---------------- LayerNorm over 324 channels + NHWC -> NCHW store (both branches) ----
__global__ __launch_bounds__(256) void ln_k(const float* __restrict__ Yin,
                                            const float* __restrict__ g,
                                            const float* __restrict__ bta,
                                            float* __restrict__ out) {
    __shared__ float tile[CH][33];
    const int br = blockIdx.y;
    const int p0 = blockIdx.x * 32;
    const float* Ybr = Yin + (size_t)br * PP * CP;
    const int cbase = br * CH;
    const int warp = threadIdx.x >> 5, lane = threadIdx.x & 31;
#pragma unroll
    for (int r = 0; r < 4; r++) {
        const int lp = warp + r * 8;
        const float* row = Ybr + (size_t)(p0 + lp) * CP;
        float vals[11];
        float s = 0.f, sq = 0.f;
#pragma unroll
        for (int j = 0; j < 11; j++) {
            const int ch = lane + j * 32;
            float v = (ch < CH) ? row[ch] : 0.f;
            vals[j] = v;
            s += v;
            sq += v * v;
        }
#pragma unroll
        for (int o = 16; o; o >>= 1) {
            s += __shfl_xor_sync(0xffffffffu, s, o);
            sq += __shfl_xor_sync(0xffffffffu, sq, o);
        }
        const float mean = s * (1.f / 324.f);
        const float var = sq * (1.f / 324.f) - mean * mean;
        const float inv = rsqrtf(var + 1e-5f);
#pragma unroll
        for (int j = 0; j < 11; j++) {
            const int ch = lane + j * 32;
            if (ch < CH)
                tile[ch][lp] = (vals[j] - mean) * inv * g[ch] + bta[ch];
        }
    }
    __syncthreads();
    const int col = threadIdx.x & 31;
    for (int ch = threadIdx.x >> 5; ch < CH; ch += 8)
        out[(size_t)(cbase + ch) * PP + p0 + col] = tile[ch][col];
}

// ---------------- launch ----------------
extern "C" void kernel_launch(void* const* d_in, const int* in_sizes, int n_in,
                              void* d_out, int out_size) {
    const float* f0  = (const float*)d_in[0];
    const float* f1  = (const float*)d_in[1];
    const float* w1  = (const float*)d_in[2];
    const float* b1  = (const float*)d_in[3];
    const float* w2  = (const float*)d_in[4];
    const float* b2  = (const float*)d_in[5];
    const float* lng = (const float*)d_in[6];
    const float* lnb = (const float*)d_in[7];
    float* out = (float*)d_out;

    float *t2;
    __half *corr0, *corr1, *f0h, *f1h, *ft, *t1, *wp1, *wp2;
    cudaGetSymbolAddress((void**)&corr0, g_corr0);
    cudaGetSymbolAddress((void**)&corr1, g_corr1);
    cudaGetSymbolAddress((void**)&f0h, g_f0h);
    cudaGetSymbolAddress((void**)&f1h, g_f1h);
    cudaGetSymbolAddress((void**)&ft, g_feat);
    cudaGetSymbolAddress((void**)&t1, g_t1);
    cudaGetSymbolAddress((void**)&t2, g_t2);
    cudaGetSymbolAddress((void**)&wp1, g_w1);
    cudaGetSymbolAddress((void**)&wp2, g_w2);

    const int gemm_smem = GST * STGHG * 2 * 2;   // 49152 B (>= 33792 B epilogue tile)
    const int conv_smem = CST * STGHC * 2 * 2;   // 61440 B
    cudaFuncSetAttribute(gemm_tc, cudaFuncAttributeMaxDynamicSharedMemorySize, gemm_smem);
    cudaFuncSetAttribute(conv_tc<0>, cudaFuncAttributeMaxDynamicSharedMemorySize, conv_smem);
    cudaFuncSetAttribute(conv_tc<1>, cudaFuncAttributeMaxDynamicSharedMemorySize, conv_smem);

    // 0,1: transpose + fp16 convert of f0/f1 -> [p][k]
    transh_k<<<dim3(200, 8), dim3(32, 8)>>>(f0, f0h);
    transh_k<<<dim3(200, 8), dim3(32, 8)>>>(f1, f1h);
    // 2: weight repack (both sets) -> [tap][co][ci] fp16
    repack_w<<<dim3((9 * CP * CIE + 255) / 256, 2), 256>>>(w1, w2, wp1, wp2);
    // 3: correlation GEMM (fp16 MMA, ldmatrix) writing corr01 and corr10
    gemm_tc<<<dim3(50, 50), 256, gemm_smem>>>(f0h, f1h, corr0, corr1);
    // 4: fused pyramid + lookup (both branches, fp16 corr in, fp16 feat out)
    pyrlook_k<<<dim3(PP, 2), 256>>>(corr0, corr1, ft);
    // 5,6: convs, both branches batched (M = 12800), fp16 MMA + ldmatrix, BK=32
    conv_tc<0><<<dim3(100, 3), 256, conv_smem>>>(ft, wp1, b1, nullptr, (void*)t1);
    conv_tc<1><<<dim3(100, 3), 256, conv_smem>>>(t1, wp2, b2, ft, (void*)t2);
    // 7: LayerNorm + transpose to NCHW
    ln_k<<<dim3(200, 2), 256>>>(t2, lng, lnb, out);
}

// round 17
// speedup vs baseline: 1.1141x; 1.0022x over previous
#include <cuda_runtime.h>
#include <cuda_fp16.h>
#include <cstdint>

#define PP 6400
#define HH 80
#define WW 80
#define KC 256      // inner dim of correlation GEMM
#define CH 324      // real channels per direction
#define CP 384      // padded channel stride
#define CIE 352     // ci loop end (324 rounded up to 32)

#define GST 4       // gemm pipeline stages (BK=16)
#define CST 3       // conv pipeline stages (BK=32)
#define PADKG 24    // gemm smem row: 16 used + 8 pad halfs (48B stride, ldsm conflict-free)
#define STGHG 3072  // gemm halfs per stage per operand: 128 * PADKG
#define PADKC 40    // conv smem row: 32 used + 8 pad halfs (80B stride, ldsm conflict-free)
#define STGHC 5120  // conv halfs per stage per operand: 128 * PADKC

// ---------------- scratch (static device globals; no allocs) ----------------
__device__ __half g_corr0[(size_t)PP * PP];   // corr01  (P, 80, 80) fp16
__device__ __half g_corr1[(size_t)PP * PP];   // corr10 = corr01^T   fp16
__device__ __half g_f0h[PP * KC];             // fp16 f0, [p][k]
__device__ __half g_f1h[PP * KC];             // fp16 f1, [q][k]
__device__ __half g_feat[2 * PP * CP];        // lookup features (fp16), both branches
__device__ __half g_t1[2 * PP * CP];          // conv1 output (fp16)
__device__ float  g_t2[2 * PP * CP];          // conv2 output (fp32)
__device__ __half g_w1[9 * CP * CIE];         // [tap][co][ci] fp16
__device__ __half g_w2[9 * CP * CIE];

// ---------------- helpers ----------------
__device__ __forceinline__ void mma_f16(float4& c,
                                        uint32_t a0, uint32_t a1, uint32_t a2, uint32_t a3,
                                        uint32_t b0, uint32_t b1) {
    asm volatile(
        "mma.sync.aligned.m16n8k16.row.col.f32.f16.f16.f32 "
        "{%0,%1,%2,%3}, {%4,%5,%6,%7}, {%8,%9}, {%0,%1,%2,%3};"
        : "+f"(c.x), "+f"(c.y), "+f"(c.z), "+f"(c.w)
        : "r"(a0), "r"(a1), "r"(a2), "r"(a3), "r"(b0), "r"(b1));
}

__device__ __forceinline__ void ldsm4(uint32_t* r, uint32_t addr) {
    asm volatile("ldmatrix.sync.aligned.m8n8.x4.shared.b16 {%0,%1,%2,%3}, [%4];"
                 : "=r"(r[0]), "=r"(r[1]), "=r"(r[2]), "=r"(r[3]) : "r"(addr));
}

__device__ __forceinline__ uint32_t su32(const void* p) {
    uint32_t a;
    asm("{ .reg .u64 t; cvta.to.shared.u64 t, %1; cvt.u32.u64 %0, t; }"
        : "=r"(a) : "l"(p));
    return a;
}

__device__ __forceinline__ void cpa16(uint32_t dst, const void* src, bool v) {
    asm volatile("cp.async.cg.shared.global [%0], [%1], 16, %2;"
                 :: "r"(dst), "l"(src), "r"(v ? 16 : 0));
}
__device__ __forceinline__ void cpa_commit() {
    asm volatile("cp.async.commit_group;");
}
template <int N>
__device__ __forceinline__ void cpa_wait() {
    asm volatile("cp.async.wait_group %0;" :: "n"(N));
}

// ---------------- transpose + fp16 convert: (KC, PP) -> [p][KC] half ----------------
__global__ void transh_k(const float* __restrict__ in, __half* __restrict__ out) {
    __shared__ float t[32][33];
    const int p0 = blockIdx.x * 32;
    const int k0 = blockIdx.y * 32;
    const int tx = threadIdx.x;
#pragma unroll
    for (int r = threadIdx.y; r < 32; r += 8)
        t[r][tx] = in[(size_t)(k0 + r) * PP + p0 + tx];
    __syncthreads();
#pragma unroll
    for (int r = threadIdx.y; r < 32; r += 8)
        out[(size_t)(p0 + r) * KC + k0 + tx] = __float2half(t[tx][r]);
}

// ---------------- weight repack: (3,3,324,324) HWIO -> [tap][co(384)][ci(352)] fp16 ----
__global__ void repack_w(const float* __restrict__ w1, const float* __restrict__ w2,
                         __half* __restrict__ wp1, __half* __restrict__ wp2) {
    const int id = blockIdx.x * blockDim.x + threadIdx.x;
    if (id >= 9 * CP * CIE) return;
    const float* w = blockIdx.y ? w2 : w1;
    __half* wp = blockIdx.y ? wp2 : wp1;
    const int ci = id % CIE;
    const int t = id / CIE;
    const int co = t % CP;
    const int tap = t / CP;
    const float v = (ci < CH && co < CH) ? w[((size_t)(tap * CH + ci)) * CH + co] : 0.f;
    wp[id] = __float2half(v);
}

// ---------------- fp16 tensor-core GEMM writing C and C^T (ldmatrix, hoisted) ---------
// A = f0h [p][KC], B = f1h [q][KC]. 128x128 tile, BK=16, GST-stage cp.async pipeline.
// 8 warps (2x4), warp tile 64x32. All 6 LDSM hoisted per slab; 16 independent MMAs.
__global__ __launch_bounds__(256) void gemm_tc(const __half* __restrict__ A,
                                               const __half* __restrict__ B,
                                               __half* __restrict__ C0,
                                               __half* __restrict__ C1) {
    extern __shared__ __align__(16) __half smh[];
    __half* Asb = smh;                      // GST stages of [128][PADKG]
    __half* Bsb = smh + GST * STGHG;
    const uint32_t asu = su32(Asb);
    const uint32_t bsu = su32(Bsb);

    const int tid = threadIdx.x;
    const int p0 = blockIdx.y * 128;
    const int q0 = blockIdx.x * 128;
    const int warp = tid >> 5, lane = tid & 31;
    const int wm = warp >> 2, wn = warp & 3;   // 2 x 4
    const int m0 = wm * 64, n0 = wn * 32;
    const int lr = lane >> 2, lc4 = lane & 3;
    const int arow = tid >> 1;              // loader row 0..127
    const int aseg = (tid & 1) * 8;         // halfs (16 B)

    // ldmatrix per-lane byte offsets within a stage
    const uint32_t aoff = (uint32_t)(((m0 + (lane & 7) + ((lane >> 3) & 1) * 8) * PADKG
                                      + ((lane >> 4) & 1) * 8) * 2);
    const uint32_t boff = (uint32_t)(((n0 + (lane & 7) + ((lane >> 4) & 1) * 8) * PADKG
                                      + ((lane >> 3) & 1) * 8) * 2);

    float4 acc[4][4];
#pragma unroll
    for (int i = 0; i < 4; i++)
#pragma unroll
        for (int j = 0; j < 4; j++) acc[i][j] = make_float4(0.f, 0.f, 0.f, 0.f);

    const __half* Ap = A + (size_t)(p0 + arow) * KC + aseg;
    const __half* Bp = B + (size_t)(q0 + arow) * KC + aseg;
    const uint32_t adst = asu + (uint32_t)(arow * PADKG + aseg) * 2;
    const uint32_t bdst = bsu + (uint32_t)(arow * PADKG + aseg) * 2;

#define GEMM_ISSUE(SLAB, BUF)                                                      \
    do {                                                                           \
        const int koff = (SLAB) * 16;                                              \
        cpa16(adst + (BUF) * (STGHG * 2), Ap + koff, true);                        \
        cpa16(bdst + (BUF) * (STGHG * 2), Bp + koff, true);                        \
        cpa_commit();                                                              \
    } while (0)

    const int NSLAB = KC / 16;   // 16
#pragma unroll
    for (int s = 0; s < GST - 1; s++) GEMM_ISSUE(s, s);

    for (int it = 0; it < NSLAB; ++it) {
        cpa_wait<GST - 2>();
        __syncthreads();
        if (it + GST - 1 < NSLAB) GEMM_ISSUE(it + GST - 1, (it + GST - 1) % GST);
        const uint32_t asf = asu + (it % GST) * (STGHG * 2);
        const uint32_t bsf = bsu + (it % GST) * (STGHG * 2);
        // hoisted fragment loads: 6 LDSM back-to-back (MLP)
        uint32_t bf01[4], bf23[4], af[4][4];
        ldsm4(bf01, bsf + boff);
        ldsm4(bf23, bsf + boff + 16 * PADKG * 2);
#pragma unroll
        for (int i = 0; i < 4; i++)
            ldsm4(af[i], asf + aoff + (uint32_t)(i * 16 * PADKG * 2));
        // 16 independent MMAs
#pragma unroll
        for (int i = 0; i < 4; i++) {
            mma_f16(acc[i][0], af[i][0], af[i][1], af[i][2], af[i][3], bf01[0], bf01[1]);
            mma_f16(acc[i][1], af[i][0], af[i][1], af[i][2], af[i][3], bf01[2], bf01[3]);
            mma_f16(acc[i][2], af[i][0], af[i][1], af[i][2], af[i][3], bf23[0], bf23[1]);
            mma_f16(acc[i][3], af[i][0], af[i][1], af[i][2], af[i][3], bf23[2], bf23[3]);
        }
    }
#undef GEMM_ISSUE

    // C0: coalesced half2 stores straight from registers
#pragma unroll
    for (int i = 0; i < 4; i++) {
        const int r = p0 + m0 + i * 16 + lr;
#pragma unroll
        for (int j = 0; j < 4; j++) {
            const int c = q0 + n0 + j * 8 + lc4 * 2;
            *(__half2*)&C0[(size_t)r * PP + c] =
                __halves2half2(__float2half(acc[i][j].x), __float2half(acc[i][j].y));
            *(__half2*)&C0[(size_t)(r + 8) * PP + c] =
                __halves2half2(__float2half(acc[i][j].z), __float2half(acc[i][j].w));
        }
    }

    // C1: smem-staged transpose, two 64-column passes, 64B-contiguous per thread
    cpa_wait<0>();
    float* tile = (float*)smh;   // 64 x 132 floats = 33792 B
#pragma unroll
    for (int pass = 0; pass < 2; pass++) {
        __syncthreads();
        if ((wn >> 1) == pass) {
            const int nloc = (wn & 1) * 32;
#pragma unroll
            for (int i = 0; i < 4; i++) {
                const int r = m0 + i * 16 + lr;
#pragma unroll
                for (int j = 0; j < 4; j++) {
                    const int cl = nloc + j * 8 + lc4 * 2;
                    tile[cl * 132 + r]           = acc[i][j].x;
                    tile[(cl + 1) * 132 + r]     = acc[i][j].y;
                    tile[cl * 132 + r + 8]       = acc[i][j].z;
                    tile[(cl + 1) * 132 + r + 8] = acc[i][j].w;
                }
            }
        }
        __syncthreads();
        const int cl2 = tid >> 2;          // 0..63 (C1 row within pass)
        const int sg = (tid & 3) * 32;     // 0,32,64,96 (p chunk)
        const float* srow = tile + cl2 * 132 + sg;
        __half2 hb[16];
#pragma unroll
        for (int u = 0; u < 16; u++)
            hb[u] = __floats2half2_rn(srow[2 * u], srow[2 * u + 1]);
        uint4* dst = (uint4*)&C1[(size_t)(q0 + pass * 64 + cl2) * PP + p0 + sg];
#pragma unroll
        for (int v = 0; v < 4; v++) dst[v] = ((const uint4*)hb)[v];
    }
}

// ---------------- fused pyramid + lookup (fp16 corr input, fp32 math, fp16 out) -------
__global__ __launch_bounds__(256) void pyrlook_k(const __half* __restrict__ corr0,
                                                 const __half* __restrict__ corr1,
                                                 __half* __restrict__ feat) {
    __shared__ float L1[1600];
    __shared__ float L2[400];
    __shared__ float L3[100];
    const int p = blockIdx.x;
    const int br = blockIdx.y;
    const __half* row = (br ? corr1 : corr0) + (size_t)p * PP;

    for (int i = threadIdx.x; i < 1600; i += 256) {
        const int y = i / 40, x = i % 40;
        const float2 a = __half22float2(*(const __half2*)(row + y * 160 + x * 2));
        const float2 b = __half22float2(*(const __half2*)(row + y * 160 + 80 + x * 2));
        L1[i] = 0.25f * (a.x + a.y + b.x + b.y);
    }
    __syncthreads();
    for (int i = threadIdx.x; i < 400; i += 256) {
        const int y = i / 20, x = i % 20;
        const float* m = L1 + y * 80 + x * 2;
        L2[i] = 0.25f * (m[0] + m[1] + m[40] + m[41]);
    }
    __syncthreads();
    for (int i = threadIdx.x; i < 100; i += 256) {
        const int y = i / 10, x = i % 10;
        const float* m = L2 + y * 40 + x * 2;
        L3[i] = 0.25f * (m[0] + m[1] + m[20] + m[21]);
    }
    __syncthreads();

    const int px = p % WW, py = p / WW;
    __half* out = feat + ((size_t)br * PP + p) * CP;
    for (int ch = threadIdx.x; ch < CP; ch += 256) {
        float v = 0.f;
        if (ch < 81) {
            const int dx = ch / 9 - 4;
            const int dy = ch % 9 - 4;
            const int ix = px + dx, iy = py + dy;
            if (((unsigned)ix < (unsigned)WW) && ((unsigned)iy < (unsigned)HH))
                v = __half2float(row[iy * WW + ix]);
        } else if (ch < CH) {
            const int lvl = ch / 81;
            const int off = ch % 81;
            const int dx = off / 9 - 4;
            const int dy = off % 9 - 4;
            const float* base;
            int hl;
            switch (lvl) {
                case 1: base = L1; hl = 40; break;
                case 2: base = L2; hl = 20; break;
                default: base = L3; hl = 10; break;
            }
            const int wl = hl;
            const float s = (float)(1 << lvl);
            const float cx = (2.f * px + 1.f) / (2.f * s) - 0.5f + (float)dx;
            const float cy = (2.f * py + 1.f) / (2.f * s) - 0.5f + (float)dy;
            const float x0f = floorf(cx), y0f = floorf(cy);
            const int ix = (int)x0f, iy = (int)y0f;
            const float fx = cx - x0f, fy = cy - y0f;
            float v00 = 0.f, v10 = 0.f, v01 = 0.f, v11 = 0.f;
            const bool xv0 = (ix >= 0) & (ix < wl);
            const bool xv1 = (ix + 1 >= 0) & (ix + 1 < wl);
            const bool yv0 = (iy >= 0) & (iy < hl);
            const bool yv1 = (iy + 1 >= 0) & (iy + 1 < hl);
            if (yv0) {
                if (xv0) v00 = base[iy * wl + ix];
                if (xv1) v10 = base[iy * wl + ix + 1];
            }
            if (yv1) {
                if (xv0) v01 = base[(iy + 1) * wl + ix];
                if (xv1) v11 = base[(iy + 1) * wl + ix + 1];
            }
            v = v00 * (1.f - fx) * (1.f - fy) + v10 * fx * (1.f - fy)
              + v01 * (1.f - fx) * fy + v11 * fx * fy;
        }
        out[ch] = __float2half(v);
    }
}

// ---------------- 3x3 conv as implicit GEMM (fp16, ldmatrix hoisted), BK=32 -----------
// M=12800 (BM=128), N=384 (BN=128), K=9 taps x 352, BK=32 (two k16 phases/slab).
// 8 warps (2x4), warp tile 64x32. Epilogue relu(acc+bias) [+res].
template <int ADD_RES>
__global__ __launch_bounds__(256, 2) void conv_tc(const __half* __restrict__ X,
                                                  const __half* __restrict__ Wt,
                                                  const float* __restrict__ bias,
                                                  const __half* __restrict__ res,
                                                  void* __restrict__ Yout) {
    extern __shared__ __align__(16) __half smh[];
    __half* Asb = smh;                      // CST stages of [128][PADKC]
    __half* Bsb = smh + CST * STGHC;
    const uint32_t asu = su32(Asb);
    const uint32_t bsu = su32(Bsb);

    const int tid = threadIdx.x;
    const int p0 = blockIdx.x * 128;
    const int c0 = blockIdx.y * 128;
    const int warp = tid >> 5, lane = tid & 31;
    const int wm = warp >> 2, wn = warp & 3;   // 2 x 4
    const int m0 = wm * 64, n0 = wn * 32;
    const int lr = lane >> 2, lc4 = lane & 3;

    const uint32_t aoff = (uint32_t)(((m0 + (lane & 7) + ((lane >> 3) & 1) * 8) * PADKC
                                      + ((lane >> 4) & 1) * 8) * 2);
    const uint32_t boff = (uint32_t)(((n0 + (lane & 7) + ((lane >> 4) & 1) * 8) * PADKC
                                      + ((lane >> 3) & 1) * 8) * 2);

    const int arow = tid >> 1;              // loader row 0..127
    const int aseg = (tid & 1) * 16;        // halfs
    const int pl = (p0 + arow) % PP;
    const int apy = pl / WW, apx = pl % WW;

    const uint32_t adst = asu + (uint32_t)(arow * PADKC + aseg) * 2;
    const uint32_t bdst = bsu + (uint32_t)(arow * PADKC + aseg) * 2;
    const __half* Xr = X + (size_t)(p0 + arow) * CP + aseg;
    const __half* Wr = Wt + (size_t)(c0 + arow) * CIE + aseg;

    float4 acc[4][4];
#pragma unroll
    for (int i = 0; i < 4; i++)
#pragma unroll
        for (int j = 0; j < 4; j++) acc[i][j] = make_float4(0.f, 0.f, 0.f, 0.f);

#define CONV_ISSUE(SLAB, BUF)                                                        \
    do {                                                                             \
        const int tap_ = (SLAB) / 11;                                                \
        const int kb_ = ((SLAB) % 11) * 32;                                          \
        const int dy = tap_ / 3 - 1, dx = tap_ % 3 - 1;                              \
        const bool valid = ((unsigned)(apy + dy) < (unsigned)HH) &&                  \
                           ((unsigned)(apx + dx) < (unsigned)WW);                    \
        const __half* xs = Xr + (size_t)(dy * WW + dx) * CP + kb_;                   \
        cpa16(adst + (BUF) * (STGHC * 2), xs, valid);                                \
        cpa16(adst + (BUF) * (STGHC * 2) + 16, xs + 8, valid);                       \
        const __half* ws = Wr + (size_t)tap_ * (CP * CIE) + kb_;                     \
        cpa16(bdst + (BUF) * (STGHC * 2), ws, true);                                 \
        cpa16(bdst + (BUF) * (STGHC * 2) + 16, ws + 8, true);                        \
        cpa_commit();                                                                \
    } while (0)

    const int NIT = 9 * 11;   // 99
#pragma unroll
    for (int s = 0; s < CST - 1; s++) CONV_ISSUE(s, s);

    for (int it = 0; it < NIT; ++it) {
        cpa_wait<CST - 2>();
        __syncthreads();
        if (it + CST - 1 < NIT) CONV_ISSUE(it + CST - 1, (it + CST - 1) % CST);
        const uint32_t asf = asu + (it % CST) * (STGHC * 2);
        const uint32_t bsf = bsu + (it % CST) * (STGHC * 2);
#pragma unroll
        for (int ks = 0; ks < 32; ks += 16) {
            // hoisted fragment loads: 6 LDSM back-to-back
            uint32_t bf01[4], bf23[4], af[4][4];
            ldsm4(bf01, bsf + boff + ks * 2);
            ldsm4(bf23, bsf + boff + ks * 2 + 16 * PADKC * 2);
#pragma unroll
            for (int i = 0; i < 4; i++)
                ldsm4(af[i], asf + aoff + ks * 2 + (uint32_t)(i * 16 * PADKC * 2));
#pragma unroll
            for (int i = 0; i < 4; i++) {
                mma_f16(acc[i][0], af[i][0], af[i][1], af[i][2], af[i][3], bf01[0], bf01[1]);
                mma_f16(acc[i][1], af[i][0], af[i][1], af[i][2], af[i][3], bf01[2], bf01[3]);
                mma_f16(acc[i][2], af[i][0], af[i][1], af[i][2], af[i][3], bf23[0], bf23[1]);
                mma_f16(acc[i][3], af[i][0], af[i][1], af[i][2], af[i][3], bf23[2], bf23[3]);
            }
        }
    }
#undef CONV_ISSUE

#pragma unroll
    for (int i = 0; i < 4; i++) {
        const int r0 = p0 + m0 + i * 16 + lr;
#pragma unroll
        for (int j = 0; j < 4; j++) {
            const int c = c0 + n0 + j * 8 + lc4 * 2;
            const float bv0 = (c < CH) ? bias[c] : 0.f;
            const float bv1 = (c + 1 < CH) ? bias[c + 1] : 0.f;
            float vx = fmaxf(acc[i][j].x + bv0, 0.f);
            float vy = fmaxf(acc[i][j].y + bv1, 0.f);
            float vz = fmaxf(acc[i][j].z + bv0, 0.f);
            float vw = fmaxf(acc[i][j].w + bv1, 0.f);
            if (ADD_RES) {
                const float2 r0v = __half22float2(*(const __half2*)&res[(size_t)r0 * CP + c]);
                const float2 r1v = __half22float2(*(const __half2*)&res[(size_t)(r0 + 8) * CP + c]);
                float* Yf = (float*)Yout;
                *(float2*)&Yf[(size_t)r0 * CP + c]       = make_float2(vx + r0v.x, vy + r0v.y);
                *(float2*)&Yf[(size_t)(r0 + 8) * CP + c] = make_float2(vz + r1v.x, vw + r1v.y);
            } else {
                __half* Yh = (__half*)Yout;
                *(__half2*)&Yh[(size_t)r0 * CP + c]       = __floats2half2_rn(vx, vy);
                *(__half2*)&Yh[(size_t)(r0 + 8) * CP + c] = __floats2half2_rn(vz, vw);
            }
        }
    }
}

// ---------------- LayerNorm over 324 channels + NHWC -> NCHW store (both branches) ----
__global__ __launch_bounds__(256) void ln_k(const float* __restrict__ Yin,
                                            const float* __restrict__ g,
                                            const float* __restrict__ bta,
                                            float* __restrict__ out) {
    __shared__ float tile[CH][33];
    const int br = blockIdx.y;
    const int p0 = blockIdx.x * 32;
    const float* Ybr = Yin + (size_t)br * PP * CP;
    const int cbase = br * CH;
    const int warp = threadIdx.x >> 5, lane = threadIdx.x & 31;
#pragma unroll
    for (int r = 0; r < 4; r++) {
        const int lp = warp + r * 8;
        const float* row = Ybr + (size_t)(p0 + lp) * CP;
        float vals[11];
        float s = 0.f, sq = 0.f;
#pragma unroll
        for (int j = 0; j < 11; j++) {
            const int ch = lane + j * 32;
            float v = (ch < CH) ? row[ch] : 0.f;
            vals[j] = v;
            s += v;
            sq += v * v;
        }
#pragma unroll
        for (int o = 16; o; o >>= 1) {
            s += __shfl_xor_sync(0xffffffffu, s, o);
            sq += __shfl_xor_sync(0xffffffffu, sq, o);
        }
        const float mean = s * (1.f / 324.f);
        const float var = sq * (1.f / 324.f) - mean * mean;
        const float inv = rsqrtf(var + 1e-5f);
#pragma unroll
        for (int j = 0; j < 11; j++) {
            const int ch = lane + j * 32;
            if (ch < CH)
                tile[ch][lp] = (vals[j] - mean) * inv * g[ch] + bta[ch];
        }
    }
    __syncthreads();
    const int col = threadIdx.x & 31;
    for (int ch = threadIdx.x >> 5; ch < CH; ch += 8)
        out[(size_t)(cbase + ch) * PP + p0 + col] = tile[ch][col];
}

// ---------------- launch ----------------
extern "C" void kernel_launch(void* const* d_in, const int* in_sizes, int n_in,
                              void* d_out, int out_size) {
    const float* f0  = (const float*)d_in[0];
    const float* f1  = (const float*)d_in[1];
    const float* w1  = (const float*)d_in[2];
    const float* b1  = (const float*)d_in[3];
    const float* w2  = (const float*)d_in[4];
    const float* b2  = (const float*)d_in[5];
    const float* lng = (const float*)d_in[6];
    const float* lnb = (const float*)d_in[7];
    float* out = (float*)d_out;

    float *t2;
    __half *corr0, *corr1, *f0h, *f1h, *ft, *t1, *wp1, *wp2;
    cudaGetSymbolAddress((void**)&corr0, g_corr0);
    cudaGetSymbolAddress((void**)&corr1, g_corr1);
    cudaGetSymbolAddress((void**)&f0h, g_f0h);
    cudaGetSymbolAddress((void**)&f1h, g_f1h);
    cudaGetSymbolAddress((void**)&ft, g_feat);
    cudaGetSymbolAddress((void**)&t1, g_t1);
    cudaGetSymbolAddress((void**)&t2, g_t2);
    cudaGetSymbolAddress((void**)&wp1, g_w1);
    cudaGetSymbolAddress((void**)&wp2, g_w2);

    const int gemm_smem = GST * STGHG * 2 * 2;   // 49152 B (>= 33792 B epilogue tile)
    const int conv_smem = CST * STGHC * 2 * 2;   // 61440 B
    cudaFuncSetAttribute(gemm_tc, cudaFuncAttributeMaxDynamicSharedMemorySize, gemm_smem);
    cudaFuncSetAttribute(conv_tc<0>, cudaFuncAttributeMaxDynamicSharedMemorySize, conv_smem);
    cudaFuncSetAttribute(conv_tc<1>, cudaFuncAttributeMaxDynamicSharedMemorySize, conv_smem);

    // 0,1: transpose + fp16 convert of f0/f1 -> [p][k]
    transh_k<<<dim3(200, 8), dim3(32, 8)>>>(f0, f0h);
    transh_k<<<dim3(200, 8), dim3(32, 8)>>>(f1, f1h);
    // 2: weight repack (both sets) -> [tap][co][ci] fp16
    repack_w<<<dim3((9 * CP * CIE + 255) / 256, 2), 256>>>(w1, w2, wp1, wp2);
    // 3: correlation GEMM (fp16 MMA, ldmatrix) writing corr01 and corr10
    gemm_tc<<<dim3(50, 50), 256, gemm_smem>>>(f0h, f1h, corr0, corr1);
    // 4: fused pyramid + lookup (both branches, fp16 corr in, fp16 feat out)
    pyrlook_k<<<dim3(PP, 2), 256>>>(corr0, corr1, ft);
    // 5,6: convs, both branches batched (M = 12800), fp16 MMA + ldmatrix, BK=32
    conv_tc<0><<<dim3(100, 3), 256, conv_smem>>>(ft, wp1, b1, nullptr, (void*)t1);
    conv_tc<1><<<dim3(100, 3), 256, conv_smem>>>(t1, wp2, b2, ft, (void*)t2);
    // 7: LayerNorm + transpose to NCHW
    ln_k<<<dim3(200, 2), 256>>>(t2, lng, lnb, out);
}